// round 11
// baseline (speedup 1.0000x reference)
#include <cuda_runtime.h>
#include <cuda_bf16.h>
#include <math.h>

#define V_   50000
#define E_   256
#define H_   256
#define G4_  1024
#define HD_  512
#define T_   50
#define B_   128
#define S_   512

typedef unsigned long long u64;
typedef unsigned int u32;

// ---------------------------------------------------------------------------
// Device scratch
// ---------------------------------------------------------------------------
__device__ __nv_bfloat16 g_embb[(size_t)V_ * E_];
__device__ __nv_bfloat16 g_wihb[(size_t)2 * G4_ * E_];
__device__ __nv_bfloat16 g_woutb[(size_t)64 * HD_];        // padded [64][512]
__device__ __nv_bfloat16 g_Gb[(size_t)2 * S_ * B_ * G4_];  // [d][s][b][j]
__device__ __nv_bfloat16 g_hb[(size_t)2 * S_ * B_ * H_];   // [d][s][b][k]
__device__ __align__(16) float g_emis[(size_t)S_ * B_ * T_];
__device__ float g_res[B_];
__device__ u32 g_barcnt[4];     // monotonic arrival counters; zeroed by k_convert

// ---------------------------------------------------------------------------
// Helpers
// ---------------------------------------------------------------------------
__device__ __forceinline__ u64 pk2(float lo, float hi) {
    u64 r; asm("mov.b64 %0, {%1, %2};" : "=l"(r) : "f"(lo), "f"(hi)); return r;
}
__device__ __forceinline__ u64 f2ma(u64 a, u64 b, u64 c) {
    u64 d; asm("fma.rn.f32x2 %0, %1, %2, %3;" : "=l"(d) : "l"(a), "l"(b), "l"(c)); return d;
}
__device__ __forceinline__ u64 f2add(u64 a, u64 b) {
    u64 d; asm("add.rn.f32x2 %0, %1, %2;" : "=l"(d) : "l"(a), "l"(b)); return d;
}
__device__ __forceinline__ float2 upk(u64 v) {
    float2 f; asm("mov.b64 {%0, %1}, %2;" : "=f"(f.x), "=f"(f.y) : "l"(v)); return f;
}
__device__ __forceinline__ u32 smem_u32(const void* p) { return (u32)__cvta_generic_to_shared(p); }
__device__ __forceinline__ void cp16(void* smem, const void* g) {
    asm volatile("cp.async.cg.shared.global [%0], [%1], 16;" :: "r"(smem_u32(smem)), "l"(g));
}
#define CP_COMMIT() asm volatile("cp.async.commit_group;")
#define CP_WAIT0()  asm volatile("cp.async.wait_group 0;")
#define CP_WAIT1()  asm volatile("cp.async.wait_group 1;")

__device__ __forceinline__ u32 bfpack(float lo, float hi) {
    u32 r; asm("cvt.rn.bf16x2.f32 %0, %1, %2;" : "=r"(r) : "f"(hi), "f"(lo)); return r;
}
__device__ __forceinline__ float tanhx(float x) {
    float r; asm("tanh.approx.f32 %0, %1;" : "=f"(r) : "f"(x)); return r;
}
__device__ __forceinline__ float sigx(float x) { return 0.5f * tanhx(0.5f * x) + 0.5f; }

__device__ __forceinline__ void ldsm4(u32& r0, u32& r1, u32& r2, u32& r3, u32 addr) {
    asm volatile("ldmatrix.sync.aligned.m8n8.x4.shared.b16 {%0,%1,%2,%3}, [%4];"
                 : "=r"(r0), "=r"(r1), "=r"(r2), "=r"(r3) : "r"(addr));
}
__device__ __forceinline__ void ldsm2(u32& r0, u32& r1, u32 addr) {
    asm volatile("ldmatrix.sync.aligned.m8n8.x2.shared.b16 {%0,%1}, [%2];"
                 : "=r"(r0), "=r"(r1) : "r"(addr));
}
__device__ __forceinline__ void hmma(float* d, u32 a0, u32 a1, u32 a2, u32 a3, u32 b0, u32 b1) {
    asm volatile(
        "mma.sync.aligned.m16n8k16.row.col.f32.bf16.bf16.f32 "
        "{%0,%1,%2,%3}, {%4,%5,%6,%7}, {%8,%9}, {%0,%1,%2,%3};"
        : "+f"(d[0]), "+f"(d[1]), "+f"(d[2]), "+f"(d[3])
        : "r"(a0), "r"(a1), "r"(a2), "r"(a3), "r"(b0), "r"(b1));
}

__device__ __forceinline__ u32 ld_acq(const u32* p) {
    u32 v; asm volatile("ld.acquire.gpu.u32 %0, [%1];" : "=r"(v) : "l"(p) : "memory"); return v;
}
__device__ __forceinline__ u32 atom_add_rel(u32* p, u32 v) {
    u32 o; asm volatile("atom.release.gpu.add.u32 %0, [%1], %2;" : "=r"(o) : "l"(p), "r"(v) : "memory"); return o;
}

// ---------------------------------------------------------------------------
// K0: convert emb + W_ih + W_out(padded to 64 rows) to bf16; reset barriers
// ---------------------------------------------------------------------------
#define EMB2  ((V_ * E_) / 2)
#define WIH2  ((G4_ * E_) / 2)
#define WOUT2 ((64 * HD_) / 2)
__global__ void __launch_bounds__(256) k_convert(
    const float* __restrict__ emb, const float* __restrict__ wf,
    const float* __restrict__ wb,  const float* __restrict__ wo)
{
    if (blockIdx.x == 0 && threadIdx.x < 4) g_barcnt[threadIdx.x] = 0;  // ordered before k_lstm (same stream)
    int i = blockIdx.x * 256 + threadIdx.x;
    if (i >= EMB2 + 2 * WIH2 + WOUT2) return;
    float2 v; __nv_bfloat162* dst;
    if (i < EMB2)                 { v = ((const float2*)emb)[i];              dst = (__nv_bfloat162*)g_embb + i; }
    else if (i < EMB2 + WIH2)     { v = ((const float2*)wf)[i - EMB2];        dst = (__nv_bfloat162*)g_wihb + (i - EMB2); }
    else if (i < EMB2 + 2 * WIH2) { v = ((const float2*)wb)[i - EMB2 - WIH2]; dst = (__nv_bfloat162*)g_wihb + (i - EMB2); }
    else {
        int j = i - EMB2 - 2 * WIH2;
        int tag = (j * 2) >> 9, k = (j * 2) & 511;
        v.x = (tag < T_) ? wo[(size_t)tag * HD_ + k] : 0.f;
        v.y = (tag < T_) ? wo[(size_t)tag * HD_ + k + 1] : 0.f;
        dst = (__nv_bfloat162*)g_woutb + j;
    }
    *dst = __floats2bfloat162_rn(v.x, v.y);
}

// ---------------------------------------------------------------------------
// K1: input projection via mma.sync bf16. grid (8 jt, 2 d, 256 sp), block 256.
// ---------------------------------------------------------------------------
__global__ void __launch_bounds__(256) k_input(
    const int* __restrict__ sent,
    const float* __restrict__ bih_f, const float* __restrict__ bhh_f,
    const float* __restrict__ bih_b, const float* __restrict__ bhh_b)
{
    extern __shared__ __align__(16) char smraw[];
    char* sm = smraw + ((1024 - (smem_u32(smraw) & 1023)) & 1023);
    char* smB  = sm;
    char* smA0 = sm + 65536;
    char* smA1 = sm + 131072;
    int*  toks0 = (int*)(sm + 196608);
    int*  toks1 = (int*)(sm + 197120);
    float* bsm  = (float*)(sm + 197632);

    const int jt = blockIdx.x, d = blockIdx.y, sp = blockIdx.z;
    const int s0 = 2 * sp, s1 = 2 * sp + 1;
    const int j0 = jt * 128;
    const int t = threadIdx.x;
    const int l = t & 31, w = t >> 5;
    const int wm = w & 3, wn = w >> 2;

    if (t < 128) {
        toks0[t] = sent[t * S_ + s0];
        toks1[t] = sent[t * S_ + s1];
        const float* bi = d ? bih_b : bih_f;
        const float* bh = d ? bhh_b : bhh_f;
        bsm[t] = bi[j0 + t] + bh[j0 + t];
    }
    __syncthreads();

    for (int i = t; i < 4096; i += 256) {
        int row = i >> 5, c = i & 31;
        cp16(smB + row * 512 + ((c ^ (row & 7)) * 16),
             (const char*)(g_wihb + ((size_t)d * G4_ + j0 + row) * E_) + c * 16);
    }
    CP_COMMIT();
    for (int i = t; i < 4096; i += 256) {
        int row = i >> 5, c = i & 31;
        cp16(smA0 + row * 512 + ((c ^ (row & 7)) * 16),
             (const char*)(g_embb + (size_t)toks0[row] * E_) + c * 16);
    }
    CP_COMMIT();
    for (int i = t; i < 4096; i += 256) {
        int row = i >> 5, c = i & 31;
        cp16(smA1 + row * 512 + ((c ^ (row & 7)) * 16),
             (const char*)(g_embb + (size_t)toks1[row] * E_) + c * 16);
    }
    CP_COMMIT();

    const u32 smB_b = smem_u32(smB);

    auto tile = [&](u32 smA_b, int s) {
        float acc[2][8][4];
#pragma unroll
        for (int m = 0; m < 2; m++)
#pragma unroll
            for (int n = 0; n < 8; n++)
#pragma unroll
                for (int q = 0; q < 4; q++) acc[m][n][q] = 0.f;

#pragma unroll 4
        for (int kk = 0; kk < 16; kk++) {
            u32 a[2][4];
#pragma unroll
            for (int m = 0; m < 2; m++) {
                int row = wm * 32 + m * 16 + (l & 15);
                int c = kk * 2 + (l >> 4);
                ldsm4(a[m][0], a[m][1], a[m][2], a[m][3],
                      smA_b + row * 512 + ((c ^ (row & 7)) * 16));
            }
#pragma unroll
            for (int nt = 0; nt < 8; nt++) {
                int row = wn * 64 + nt * 8 + (l & 7);
                int c = kk * 2 + ((l >> 3) & 1);
                u32 b0, b1;
                ldsm2(b0, b1, smB_b + row * 512 + ((c ^ (row & 7)) * 16));
#pragma unroll
                for (int m = 0; m < 2; m++)
                    hmma(acc[m][nt], a[m][0], a[m][1], a[m][2], a[m][3], b0, b1);
            }
        }

        __nv_bfloat16* Gbase = g_Gb + ((size_t)(d * S_ + s) * B_) * G4_;
#pragma unroll
        for (int m = 0; m < 2; m++)
#pragma unroll
        for (int nt = 0; nt < 8; nt++) {
            int r  = wm * 32 + m * 16 + (l >> 2);
            int jl = wn * 64 + nt * 8 + 2 * (l & 3);
            float b0 = bsm[jl], b1 = bsm[jl + 1];
            *(u32*)(Gbase + (size_t)r * G4_ + j0 + jl)       = bfpack(acc[m][nt][0] + b0, acc[m][nt][1] + b1);
            *(u32*)(Gbase + (size_t)(r + 8) * G4_ + j0 + jl) = bfpack(acc[m][nt][2] + b0, acc[m][nt][3] + b1);
        }
    };

    CP_WAIT1();
    __syncthreads();
    tile(smem_u32(smA0), s0);
    CP_WAIT0();
    __syncthreads();
    tile(smem_u32(smA1), s1);
}

// ---------------------------------------------------------------------------
// K2: persistent bidirectional LSTM — fused batch halves on separate warps.
// grid 64 (d = cta>>5, slice = cta&31), block 256 = two 128-thread halves.
// Half wh handles batch half wh: M=64, N=32, K=256, own smem tile + own
// grid-barrier group (grp = d*2 + wh, 32 arrivals, monotonic counter).
// Halves sync via named barriers only -> HW warp scheduler anti-phases them.
// ---------------------------------------------------------------------------
__global__ void __launch_bounds__(256, 1) k_lstm(
    const float* __restrict__ whh_f, const float* __restrict__ whh_b)
{
    extern __shared__ __align__(16) char smraw[];
    char* sm = smraw + ((1024 - (smem_u32(smraw) & 1023)) & 1023);
    char* smW = sm;                        // 16KB W_hh slice [32][256] bf16 (shared)
    const int t  = threadIdx.x;
    const int wh = t >> 7;                 // batch half 0/1
    const int lt = t & 127;                // tid within half
    char* smA = sm + 16384 + wh * 32768;   // 32KB h tile per half

    const int cta   = blockIdx.x;
    const int d     = cta >> 5;
    const int slice = cta & 31;
    const int n0    = slice * 8;
    const int grp   = d * 2 + wh;
    const int l = t & 31, w = (lt >> 5);
    const float* __restrict__ Wh = d ? whh_b : whh_f;

    for (int i = t; i < 8192; i += 256) {
        int row = i >> 8, k = i & 255;
        int j = ((row >> 3) * 256) + n0 + (row & 7);
        int c = k >> 3;
        *(__nv_bfloat16*)(smW + row * 512 + ((c ^ (row & 7)) * 16) + (k & 7) * 2) =
            __float2bfloat16(Wh[(size_t)j * H_ + k]);
    }
    {   // zero both h tiles (step-0 h_prev = 0)
        uint4 z = make_uint4(0, 0, 0, 0);
        uint4* tiles = (uint4*)(sm + 16384);
        for (int i = t; i < 4096; i += 256) tiles[i] = z;
    }
    __syncthreads();   // only full-block sync; halves diverge after this

#define HBAR() asm volatile("bar.sync %0, 128;" :: "r"(1 + wh) : "memory")

    const u32 smA_b = smem_u32(smA), smW_b = smem_u32(smW);
    const int qbl = w * 16 + (l >> 2);       // local b (and +8)
    const int u0  = 2 * (l & 3);
    const int bh  = wh;

    float cst[4];
#pragma unroll
    for (int u = 0; u < 4; u++) cst[u] = 0.f;

    const __nv_bfloat16* Gd = g_Gb + (size_t)d * S_ * B_ * G4_;
    __nv_bfloat16*       Hd = g_hb + (size_t)d * S_ * B_ * H_;

    u32 gq[8], gqn[8];
    {
        const __nv_bfloat16* Gp = Gd + (size_t)(d ? S_ - 1 : 0) * B_ * G4_;
#pragma unroll
        for (int i = 0; i < 2; i++) {
            int b = bh * 64 + qbl + 8 * i;
#pragma unroll
            for (int gg = 0; gg < 4; gg++)
                gqn[i * 4 + gg] = *(const u32*)(Gp + (size_t)b * G4_ + gg * 256 + n0 + u0);
        }
    }

    for (int step = 0; step < S_; step++) {
        const int s = d ? (S_ - 1 - step) : step;

#pragma unroll
        for (int j = 0; j < 8; j++) gq[j] = gqn[j];
        if (step + 1 < S_) {
            const int sn = d ? (S_ - 2 - step) : (step + 1);
            const __nv_bfloat16* Gp = Gd + (size_t)sn * B_ * G4_;
#pragma unroll
            for (int i = 0; i < 2; i++) {
                int b = bh * 64 + qbl + 8 * i;
#pragma unroll
                for (int gg = 0; gg < 4; gg++)
                    gqn[i * 4 + gg] = *(const u32*)(Gp + (size_t)b * G4_ + gg * 256 + n0 + u0);
            }
        }

        if (step > 0) {
            const char* hsrc = (const char*)(Hd + ((size_t)(d ? s + 1 : s - 1) * B_ + bh * 64) * H_);
            for (int i = lt; i < 1024; i += 128) {
                int row = i >> 4, c = i & 15;
                cp16(smA + row * 512 + ((c ^ (row & 7)) * 16), hsrc + row * 512 + c * 16);
            }
            CP_COMMIT();
            for (int i = lt; i < 1024; i += 128) {
                int row = i >> 4, c = (i & 15) + 16;
                cp16(smA + row * 512 + ((c ^ (row & 7)) * 16), hsrc + row * 512 + c * 16);
            }
            CP_COMMIT();
        }

        float acc[4][4];
#pragma unroll
        for (int g = 0; g < 4; g++)
#pragma unroll
            for (int q = 0; q < 4; q++) acc[g][q] = 0.f;

        CP_WAIT1();
        HBAR();
#pragma unroll
        for (int kk = 0; kk < 8; kk++) {
            u32 a0r, a1r, a2r, a3r;
            {
                int row = w * 16 + (l & 15);
                int c = kk * 2 + (l >> 4);
                ldsm4(a0r, a1r, a2r, a3r, smA_b + row * 512 + ((c ^ (row & 7)) * 16));
            }
#pragma unroll
            for (int g = 0; g < 4; g++) {
                int row = g * 8 + (l & 7);
                int c = kk * 2 + ((l >> 3) & 1);
                u32 b0, b1;
                ldsm2(b0, b1, smW_b + row * 512 + ((c ^ (row & 7)) * 16));
                hmma(acc[g], a0r, a1r, a2r, a3r, b0, b1);
            }
        }
        CP_WAIT0();
        HBAR();
#pragma unroll
        for (int kk = 8; kk < 16; kk++) {
            u32 a0r, a1r, a2r, a3r;
            {
                int row = w * 16 + (l & 15);
                int c = kk * 2 + (l >> 4);
                ldsm4(a0r, a1r, a2r, a3r, smA_b + row * 512 + ((c ^ (row & 7)) * 16));
            }
#pragma unroll
            for (int g = 0; g < 4; g++) {
                int row = g * 8 + (l & 7);
                int c = kk * 2 + ((l >> 3) & 1);
                u32 b0, b1;
                ldsm2(b0, b1, smW_b + row * 512 + ((c ^ (row & 7)) * 16));
                hmma(acc[g], a0r, a1r, a2r, a3r, b0, b1);
            }
        }

        // combine + store h
#pragma unroll
        for (int i = 0; i < 2; i++) {
            const int bl = qbl + 8 * i;
            const int e = 2 * i;
            float2 gi = __bfloat1622float2(*(const __nv_bfloat162*)&gq[i * 4 + 0]);
            float2 gf = __bfloat1622float2(*(const __nv_bfloat162*)&gq[i * 4 + 1]);
            float2 gg = __bfloat1622float2(*(const __nv_bfloat162*)&gq[i * 4 + 2]);
            float2 go = __bfloat1622float2(*(const __nv_bfloat162*)&gq[i * 4 + 3]);
            const int ci = 2 * i;
            float c0 = sigx(acc[1][e] + gf.x) * cst[ci]
                     + sigx(acc[0][e] + gi.x) * tanhx(acc[2][e] + gg.x);
            cst[ci] = c0;
            float h0 = sigx(acc[3][e] + go.x) * tanhx(c0);
            float c1 = sigx(acc[1][e + 1] + gf.y) * cst[ci + 1]
                     + sigx(acc[0][e + 1] + gi.y) * tanhx(acc[2][e + 1] + gg.y);
            cst[ci + 1] = c1;
            float h1 = sigx(acc[3][e + 1] + go.y) * tanhx(c1);
            *(u32*)(Hd + ((size_t)s * B_ + bh * 64 + bl) * H_ + n0 + u0) = bfpack(h0, h1);
        }

        // per-half monotonic-counter grid barrier (group of 32 CTAs)
        if (step != S_ - 1) {
            HBAR();
            if (lt == 0) {
                atom_add_rel(&g_barcnt[grp], 1);
                const u32 tgt = (u32)(32 * (step + 1));
                while ((int)(ld_acq(&g_barcnt[grp]) - tgt) < 0) { __nanosleep(20); }
            }
            HBAR();
        }
    }
#undef HBAR
}

// ---------------------------------------------------------------------------
// K3: emissions via mma.sync. grid 512 (s), block 128.
// ---------------------------------------------------------------------------
__global__ void __launch_bounds__(128) k_emis(const float* __restrict__ bo)
{
    extern __shared__ __align__(16) char smraw[];
    char* sm = smraw + ((1024 - (smem_u32(smraw) & 1023)) & 1023);
    char* smW  = sm;
    char* smA0 = sm + 65536;
    char* smA1 = sm + 131072;
    float* bsm = (float*)(sm + 196608);

    const int s = blockIdx.x;
    const int t = threadIdx.x;
    const int l = t & 31, w = t >> 5;

    if (t < 64) bsm[t] = (t < T_) ? bo[t] : 0.f;

    for (int i = t; i < 4096; i += 128) {
        int row = i >> 6, c = i & 63;
        cp16(smW + row * 1024 + ((c ^ (row & 7)) * 16),
             (const char*)g_woutb + row * 1024 + c * 16);
    }
    CP_COMMIT();
    for (int i = t; i < 4096; i += 128) {
        int row = i >> 5, c = i & 31;
        cp16(smA0 + row * 512 + ((c ^ (row & 7)) * 16),
             (const char*)(g_hb + ((size_t)s * B_ + row) * H_) + c * 16);
    }
    CP_COMMIT();
    for (int i = t; i < 4096; i += 128) {
        int row = i >> 5, c = i & 31;
        cp16(smA1 + row * 512 + ((c ^ (row & 7)) * 16),
             (const char*)(g_hb + (size_t)S_ * B_ * H_ + ((size_t)s * B_ + row) * H_) + c * 16);
    }
    CP_COMMIT();

    const u32 smW_b = smem_u32(smW);

    float acc[2][8][4];
#pragma unroll
    for (int m = 0; m < 2; m++)
#pragma unroll
        for (int n = 0; n < 8; n++)
#pragma unroll
            for (int q = 0; q < 4; q++) acc[m][n][q] = 0.f;

    auto stage = [&](u32 smA_b, int wc0) {
#pragma unroll 4
        for (int kk = 0; kk < 16; kk++) {
            u32 a[2][4];
#pragma unroll
            for (int m = 0; m < 2; m++) {
                int row = w * 32 + m * 16 + (l & 15);
                int c = kk * 2 + (l >> 4);
                ldsm4(a[m][0], a[m][1], a[m][2], a[m][3],
                      smA_b + row * 512 + ((c ^ (row & 7)) * 16));
            }
#pragma unroll
            for (int nt = 0; nt < 8; nt++) {
                int row = nt * 8 + (l & 7);
                int c = wc0 + kk * 2 + ((l >> 3) & 1);
                u32 b0, b1;
                ldsm2(b0, b1, smW_b + row * 1024 + ((c ^ (row & 7)) * 16));
#pragma unroll
                for (int m = 0; m < 2; m++)
                    hmma(acc[m][nt], a[m][0], a[m][1], a[m][2], a[m][3], b0, b1);
            }
        }
    };

    CP_WAIT1();
    __syncthreads();
    stage(smem_u32(smA0), 0);
    CP_WAIT0();
    __syncthreads();
    stage(smem_u32(smA1), 32);

#pragma unroll
    for (int m = 0; m < 2; m++)
#pragma unroll
    for (int nt = 0; nt < 8; nt++) {
        int r  = w * 32 + m * 16 + (l >> 2);
        int jl = nt * 8 + 2 * (l & 3);
        if (jl < T_) {
            float b0 = bsm[jl], b1 = bsm[jl + 1];
            *(float2*)(g_emis + ((size_t)s * B_ + r) * T_ + jl)     = make_float2(acc[m][nt][0] + b0, acc[m][nt][1] + b1);
            *(float2*)(g_emis + ((size_t)s * B_ + r + 8) * T_ + jl) = make_float2(acc[m][nt][2] + b0, acc[m][nt][3] + b1);
        }
    }
}

// ---------------------------------------------------------------------------
// K4: CRF — one warp per batch element, 128 CTAs.
// ---------------------------------------------------------------------------
__global__ void __launch_bounds__(32) k_crf(
    const float* __restrict__ trans, const float* __restrict__ start_t,
    const float* __restrict__ end_t, const int* __restrict__ tags)
{
    __shared__ __align__(16) u64 Esp[T_ * 32];
    __shared__ float pw[64];

    const int b = blockIdx.x;
    const int l = threadIdx.x;

    for (int i = l; i < T_ * 32; i += 32) {
        int tt = i >> 5, c = i & 31;
        float e0 = expf(trans[tt * T_ + c]);
        float e1 = (c + 32 < T_) ? expf(trans[tt * T_ + c + 32]) : 0.f;
        Esp[i] = pk2(e0, e1);
    }
    __syncwarp();

    const bool v1 = (l + 32 < T_);
    float a0 = start_t[l] + g_emis[(size_t)b * T_ + l];
    float a1 = v1 ? (start_t[l + 32] + g_emis[(size_t)b * T_ + l + 32]) : -1e30f;

    float e0n = g_emis[((size_t)B_ + b) * T_ + l];
    float e1n = v1 ? g_emis[((size_t)B_ + b) * T_ + l + 32] : 0.f;

    for (int s = 1; s < S_; s++) {
        float e0 = e0n, e1 = e1n;
        if (s + 1 < S_) {
            const float* es = g_emis + ((size_t)(s + 1) * B_ + b) * T_;
            e0n = es[l];
            e1n = v1 ? es[l + 32] : 0.f;
        }

        float m = __shfl_sync(0xffffffffu, a0, 0);
        pw[l]      = __expf(a0 - m);
        pw[l + 32] = v1 ? __expf(a1 - m) : 0.f;
        __syncwarp();

        u64 q0 = 0ull, q1 = 0ull, q2 = 0ull, q3 = 0ull;
#pragma unroll
        for (int tt = 0; tt < 48; tt += 4) {
            q0 = f2ma(pk2(pw[tt],     pw[tt]),     Esp[(tt)     * 32 + l], q0);
            q1 = f2ma(pk2(pw[tt + 1], pw[tt + 1]), Esp[(tt + 1) * 32 + l], q1);
            q2 = f2ma(pk2(pw[tt + 2], pw[tt + 2]), Esp[(tt + 2) * 32 + l], q2);
            q3 = f2ma(pk2(pw[tt + 3], pw[tt + 3]), Esp[(tt + 3) * 32 + l], q3);
        }
        q0 = f2ma(pk2(pw[48], pw[48]), Esp[48 * 32 + l], q0);
        q1 = f2ma(pk2(pw[49], pw[49]), Esp[49 * 32 + l], q1);
        float2 qf = upk(f2add(f2add(q0, q1), f2add(q2, q3)));
        a0 = m + __logf(qf.x) + e0;
        a1 = v1 ? (m + __logf(qf.y) + e1) : -1e30f;
        __syncwarp();
    }

    float vv0 = a0 + end_t[l];
    float vv1 = v1 ? (a1 + end_t[l + 32]) : -1e30f;
    float m = fmaxf(vv0, vv1);
#pragma unroll
    for (int o = 16; o; o >>= 1) m = fmaxf(m, __shfl_xor_sync(0xffffffffu, m, o));
    float e = __expf(vv0 - m) + (v1 ? __expf(vv1 - m) : 0.f);
#pragma unroll
    for (int o = 16; o; o >>= 1) e += __shfl_xor_sync(0xffffffffu, e, o);
    float logZ = m + __logf(e);

    float acc = 0.f;
    for (int s = 1 + l; s < S_; s += 32) {
        int tp = tags[b * S_ + s - 1];
        int tc = tags[b * S_ + s];
        acc += trans[tp * T_ + tc] + g_emis[((size_t)s * B_ + b) * T_ + tc];
    }
#pragma unroll
    for (int o = 16; o; o >>= 1) acc += __shfl_xor_sync(0xffffffffu, acc, o);

    if (l == 0) {
        int t0 = tags[b * S_];
        int tl = tags[b * S_ + S_ - 1];
        g_res[b] = logZ - (start_t[t0] + g_emis[(size_t)b * T_ + t0] + acc + end_t[tl]);
    }
}

// ---------------------------------------------------------------------------
// K5: final mean
// ---------------------------------------------------------------------------
__global__ void k_final(float* __restrict__ out)
{
    __shared__ float red[4];
    int t = threadIdx.x;
    float v = g_res[t];
#pragma unroll
    for (int o = 16; o; o >>= 1) v += __shfl_xor_sync(0xffffffffu, v, o);
    if ((t & 31) == 0) red[t >> 5] = v;
    __syncthreads();
    if (t == 0) out[0] = (red[0] + red[1] + red[2] + red[3]) * (1.f / (float)B_);
}

// ---------------------------------------------------------------------------
// Launch
// ---------------------------------------------------------------------------
extern "C" void kernel_launch(void* const* d_in, const int* in_sizes, int n_in,
                              void* d_out, int out_size)
{
    const int*   sent  = (const int*)  d_in[0];
    const int*   tags  = (const int*)  d_in[1];
    const float* emb   = (const float*)d_in[3];
    const float* wih_f = (const float*)d_in[4];
    const float* whh_f = (const float*)d_in[5];
    const float* bih_f = (const float*)d_in[6];
    const float* bhh_f = (const float*)d_in[7];
    const float* wih_b = (const float*)d_in[8];
    const float* whh_b = (const float*)d_in[9];
    const float* bih_b = (const float*)d_in[10];
    const float* bhh_b = (const float*)d_in[11];
    const float* Wout  = (const float*)d_in[12];
    const float* bout  = (const float*)d_in[13];
    const float* strt  = (const float*)d_in[14];
    const float* endt  = (const float*)d_in[15];
    const float* trans = (const float*)d_in[16];
    float* out = (float*)d_out;

    const int input_smem = 199168;
    const int lstm_smem  = 16384 + 65536 + 1024;   // W + 2 half-tiles + align
    const int emis_smem  = 197888;
    cudaFuncSetAttribute(k_input, cudaFuncAttributeMaxDynamicSharedMemorySize, input_smem);
    cudaFuncSetAttribute(k_lstm,  cudaFuncAttributeMaxDynamicSharedMemorySize, lstm_smem);
    cudaFuncSetAttribute(k_emis,  cudaFuncAttributeMaxDynamicSharedMemorySize, emis_smem);

    int nconv = (EMB2 + 2 * WIH2 + WOUT2 + 255) / 256;
    k_convert<<<nconv, 256>>>(emb, wih_f, wih_b, Wout);
    k_input<<<dim3(8, 2, 256), 256, input_smem>>>(sent, bih_f, bhh_f, bih_b, bhh_b);
    k_lstm<<<64, 256, lstm_smem>>>(whh_f, whh_b);
    k_emis<<<512, 128, emis_smem>>>(bout);
    k_crf<<<128, 32>>>(trans, strt, endt, tags);
    k_final<<<1, 128>>>(out);
}

// round 12
// speedup vs baseline: 1.0473x; 1.0473x over previous
#include <cuda_runtime.h>
#include <cuda_bf16.h>
#include <math.h>

#define V_   50000
#define E_   256
#define H_   256
#define G4_  1024
#define HD_  512
#define T_   50
#define B_   128
#define S_   512

typedef unsigned long long u64;
typedef unsigned int u32;

// ---------------------------------------------------------------------------
// Device scratch
// ---------------------------------------------------------------------------
__device__ __nv_bfloat16 g_embb[(size_t)V_ * E_];
__device__ __nv_bfloat16 g_wihb[(size_t)2 * G4_ * E_];
__device__ __nv_bfloat16 g_woutb[(size_t)64 * HD_];        // padded [64][512]
__device__ __nv_bfloat16 g_Gb[(size_t)2 * S_ * B_ * G4_];  // [d][s][b][j]
__device__ __nv_bfloat16 g_hb[(size_t)2 * S_ * B_ * H_];   // [d][s][b][k]
__device__ __align__(16) float g_emis[(size_t)S_ * B_ * T_];
__device__ float g_res[B_];
__device__ u32 g_barcnt[4];     // monotonic arrival counters; zeroed by k_convert

// ---------------------------------------------------------------------------
// Helpers
// ---------------------------------------------------------------------------
__device__ __forceinline__ u64 pk2(float lo, float hi) {
    u64 r; asm("mov.b64 %0, {%1, %2};" : "=l"(r) : "f"(lo), "f"(hi)); return r;
}
__device__ __forceinline__ u64 f2ma(u64 a, u64 b, u64 c) {
    u64 d; asm("fma.rn.f32x2 %0, %1, %2, %3;" : "=l"(d) : "l"(a), "l"(b), "l"(c)); return d;
}
__device__ __forceinline__ u64 f2add(u64 a, u64 b) {
    u64 d; asm("add.rn.f32x2 %0, %1, %2;" : "=l"(d) : "l"(a), "l"(b)); return d;
}
__device__ __forceinline__ float2 upk(u64 v) {
    float2 f; asm("mov.b64 {%0, %1}, %2;" : "=f"(f.x), "=f"(f.y) : "l"(v)); return f;
}
__device__ __forceinline__ u32 smem_u32(const void* p) { return (u32)__cvta_generic_to_shared(p); }
__device__ __forceinline__ void cp16(void* smem, const void* g) {
    asm volatile("cp.async.cg.shared.global [%0], [%1], 16;" :: "r"(smem_u32(smem)), "l"(g));
}
#define CP_COMMIT() asm volatile("cp.async.commit_group;")
#define CP_WAIT0()  asm volatile("cp.async.wait_group 0;")
#define CP_WAIT1()  asm volatile("cp.async.wait_group 1;")

__device__ __forceinline__ u32 bfpack(float lo, float hi) {
    u32 r; asm("cvt.rn.bf16x2.f32 %0, %1, %2;" : "=r"(r) : "f"(hi), "f"(lo)); return r;
}

// ---- MUFU-free activations (fma/alu pipes only) ----
// exp(x) via 2^z with magic-number round: valid for |x| <= ~85
__device__ __forceinline__ float fexpx(float x) {
    float z = x * 1.4426950408889634f;
    float t = z + 12582912.0f;                  // 1.5*2^23 magic
    int   i = __float_as_int(t) - 0x4B400000;   // round(z)
    float f = z - (t - 12582912.0f);            // frac in [-0.5, 0.5]
    float p =      1.3333558e-3f;
    p = fmaf(p, f, 9.6181291e-3f);
    p = fmaf(p, f, 5.5504109e-2f);
    p = fmaf(p, f, 2.4022651e-1f);
    p = fmaf(p, f, 6.9314718e-1f);
    p = fmaf(p, f, 1.0f);
    return __int_as_float(__float_as_int(p) + (i << 23));
}
// reciprocal for x >= ~1 via bit-seed + 2 Newton steps (err ~1e-6)
__device__ __forceinline__ float frcpx(float x) {
    float y = __int_as_float(0x7EF311C3 - __float_as_int(x));
    y = y * fmaf(-x, y, 2.0f);
    y = y * fmaf(-x, y, 2.0f);
    return y;
}
__device__ __forceinline__ float fsig(float x) {
    x = fminf(fmaxf(x, -80.f), 80.f);
    return frcpx(1.0f + fexpx(-x));
}
__device__ __forceinline__ float ftanh(float x) {
    x = fminf(fmaxf(x, -40.f), 40.f);
    return fmaf(2.0f, frcpx(1.0f + fexpx(-2.0f * x)), -1.0f);
}

__device__ __forceinline__ void ldsm4(u32& r0, u32& r1, u32& r2, u32& r3, u32 addr) {
    asm volatile("ldmatrix.sync.aligned.m8n8.x4.shared.b16 {%0,%1,%2,%3}, [%4];"
                 : "=r"(r0), "=r"(r1), "=r"(r2), "=r"(r3) : "r"(addr));
}
__device__ __forceinline__ void ldsm2(u32& r0, u32& r1, u32 addr) {
    asm volatile("ldmatrix.sync.aligned.m8n8.x2.shared.b16 {%0,%1}, [%2];"
                 : "=r"(r0), "=r"(r1) : "r"(addr));
}
__device__ __forceinline__ void hmma(float* d, u32 a0, u32 a1, u32 a2, u32 a3, u32 b0, u32 b1) {
    asm volatile(
        "mma.sync.aligned.m16n8k16.row.col.f32.bf16.bf16.f32 "
        "{%0,%1,%2,%3}, {%4,%5,%6,%7}, {%8,%9}, {%0,%1,%2,%3};"
        : "+f"(d[0]), "+f"(d[1]), "+f"(d[2]), "+f"(d[3])
        : "r"(a0), "r"(a1), "r"(a2), "r"(a3), "r"(b0), "r"(b1));
}

__device__ __forceinline__ u32 ld_acq(const u32* p) {
    u32 v; asm volatile("ld.acquire.gpu.u32 %0, [%1];" : "=r"(v) : "l"(p) : "memory"); return v;
}
__device__ __forceinline__ u32 atom_add_rel(u32* p, u32 v) {
    u32 o; asm volatile("atom.release.gpu.add.u32 %0, [%1], %2;" : "=r"(o) : "l"(p), "r"(v) : "memory"); return o;
}

// ---------------------------------------------------------------------------
// K0: convert emb + W_ih + W_out(padded to 64 rows) to bf16; reset barriers
// ---------------------------------------------------------------------------
#define EMB2  ((V_ * E_) / 2)
#define WIH2  ((G4_ * E_) / 2)
#define WOUT2 ((64 * HD_) / 2)
__global__ void __launch_bounds__(256) k_convert(
    const float* __restrict__ emb, const float* __restrict__ wf,
    const float* __restrict__ wb,  const float* __restrict__ wo)
{
    if (blockIdx.x == 0 && threadIdx.x < 4) g_barcnt[threadIdx.x] = 0;  // ordered before k_lstm (same stream)
    int i = blockIdx.x * 256 + threadIdx.x;
    if (i >= EMB2 + 2 * WIH2 + WOUT2) return;
    float2 v; __nv_bfloat162* dst;
    if (i < EMB2)                 { v = ((const float2*)emb)[i];              dst = (__nv_bfloat162*)g_embb + i; }
    else if (i < EMB2 + WIH2)     { v = ((const float2*)wf)[i - EMB2];        dst = (__nv_bfloat162*)g_wihb + (i - EMB2); }
    else if (i < EMB2 + 2 * WIH2) { v = ((const float2*)wb)[i - EMB2 - WIH2]; dst = (__nv_bfloat162*)g_wihb + (i - EMB2); }
    else {
        int j = i - EMB2 - 2 * WIH2;
        int tag = (j * 2) >> 9, k = (j * 2) & 511;
        v.x = (tag < T_) ? wo[(size_t)tag * HD_ + k] : 0.f;
        v.y = (tag < T_) ? wo[(size_t)tag * HD_ + k + 1] : 0.f;
        dst = (__nv_bfloat162*)g_woutb + j;
    }
    *dst = __floats2bfloat162_rn(v.x, v.y);
}

// ---------------------------------------------------------------------------
// K1: input projection via mma.sync bf16. grid (8 jt, 2 d, 256 sp), block 256.
// ---------------------------------------------------------------------------
__global__ void __launch_bounds__(256) k_input(
    const int* __restrict__ sent,
    const float* __restrict__ bih_f, const float* __restrict__ bhh_f,
    const float* __restrict__ bih_b, const float* __restrict__ bhh_b)
{
    extern __shared__ __align__(16) char smraw[];
    char* sm = smraw + ((1024 - (smem_u32(smraw) & 1023)) & 1023);
    char* smB  = sm;
    char* smA0 = sm + 65536;
    char* smA1 = sm + 131072;
    int*  toks0 = (int*)(sm + 196608);
    int*  toks1 = (int*)(sm + 197120);
    float* bsm  = (float*)(sm + 197632);

    const int jt = blockIdx.x, d = blockIdx.y, sp = blockIdx.z;
    const int s0 = 2 * sp, s1 = 2 * sp + 1;
    const int j0 = jt * 128;
    const int t = threadIdx.x;
    const int l = t & 31, w = t >> 5;
    const int wm = w & 3, wn = w >> 2;

    if (t < 128) {
        toks0[t] = sent[t * S_ + s0];
        toks1[t] = sent[t * S_ + s1];
        const float* bi = d ? bih_b : bih_f;
        const float* bh = d ? bhh_b : bhh_f;
        bsm[t] = bi[j0 + t] + bh[j0 + t];
    }
    __syncthreads();

    for (int i = t; i < 4096; i += 256) {
        int row = i >> 5, c = i & 31;
        cp16(smB + row * 512 + ((c ^ (row & 7)) * 16),
             (const char*)(g_wihb + ((size_t)d * G4_ + j0 + row) * E_) + c * 16);
    }
    CP_COMMIT();
    for (int i = t; i < 4096; i += 256) {
        int row = i >> 5, c = i & 31;
        cp16(smA0 + row * 512 + ((c ^ (row & 7)) * 16),
             (const char*)(g_embb + (size_t)toks0[row] * E_) + c * 16);
    }
    CP_COMMIT();
    for (int i = t; i < 4096; i += 256) {
        int row = i >> 5, c = i & 31;
        cp16(smA1 + row * 512 + ((c ^ (row & 7)) * 16),
             (const char*)(g_embb + (size_t)toks1[row] * E_) + c * 16);
    }
    CP_COMMIT();

    const u32 smB_b = smem_u32(smB);

    auto tile = [&](u32 smA_b, int s) {
        float acc[2][8][4];
#pragma unroll
        for (int m = 0; m < 2; m++)
#pragma unroll
            for (int n = 0; n < 8; n++)
#pragma unroll
                for (int q = 0; q < 4; q++) acc[m][n][q] = 0.f;

#pragma unroll 4
        for (int kk = 0; kk < 16; kk++) {
            u32 a[2][4];
#pragma unroll
            for (int m = 0; m < 2; m++) {
                int row = wm * 32 + m * 16 + (l & 15);
                int c = kk * 2 + (l >> 4);
                ldsm4(a[m][0], a[m][1], a[m][2], a[m][3],
                      smA_b + row * 512 + ((c ^ (row & 7)) * 16));
            }
#pragma unroll
            for (int nt = 0; nt < 8; nt++) {
                int row = wn * 64 + nt * 8 + (l & 7);
                int c = kk * 2 + ((l >> 3) & 1);
                u32 b0, b1;
                ldsm2(b0, b1, smB_b + row * 512 + ((c ^ (row & 7)) * 16));
#pragma unroll
                for (int m = 0; m < 2; m++)
                    hmma(acc[m][nt], a[m][0], a[m][1], a[m][2], a[m][3], b0, b1);
            }
        }

        __nv_bfloat16* Gbase = g_Gb + ((size_t)(d * S_ + s) * B_) * G4_;
#pragma unroll
        for (int m = 0; m < 2; m++)
#pragma unroll
        for (int nt = 0; nt < 8; nt++) {
            int r  = wm * 32 + m * 16 + (l >> 2);
            int jl = wn * 64 + nt * 8 + 2 * (l & 3);
            float b0 = bsm[jl], b1 = bsm[jl + 1];
            *(u32*)(Gbase + (size_t)r * G4_ + j0 + jl)       = bfpack(acc[m][nt][0] + b0, acc[m][nt][1] + b1);
            *(u32*)(Gbase + (size_t)(r + 8) * G4_ + j0 + jl) = bfpack(acc[m][nt][2] + b0, acc[m][nt][3] + b1);
        }
    };

    CP_WAIT1();
    __syncthreads();
    tile(smem_u32(smA0), s0);
    CP_WAIT0();
    __syncthreads();
    tile(smem_u32(smA1), s1);
}

// ---------------------------------------------------------------------------
// K2: persistent bidirectional LSTM (R10 structure). grid 128, block 128.
// CTA = (d = cta>>6, bhalf = (cta>>5)&1, slice = cta&31). M=64, N=32, K=256.
// 4 independent groups of 32 CTAs; monotonic-counter barrier.
// Activations are MUFU-free (fma/alu pipes) — MUFU was the per-step wall.
// ---------------------------------------------------------------------------
__global__ void __launch_bounds__(128, 1) k_lstm(
    const float* __restrict__ whh_f, const float* __restrict__ whh_b)
{
    extern __shared__ __align__(16) char smraw[];
    char* sm = smraw + ((1024 - (smem_u32(smraw) & 1023)) & 1023);
    char* smA = sm;                  // 32KB h tile [64 b][512B]
    char* smW = sm + 32768;          // 16KB W_hh slice [32][256] bf16

    const int cta   = blockIdx.x;
    const int d     = cta >> 6;
    const int bh    = (cta >> 5) & 1;
    const int slice = cta & 31;
    const int n0    = slice * 8;
    const int grp   = cta >> 5;      // 0..3
    const int t     = threadIdx.x;
    const int l = t & 31, w = t >> 5;
    const float* __restrict__ Wh = d ? whh_b : whh_f;

    for (int i = t; i < 8192; i += 128) {
        int row = i >> 8, k = i & 255;
        int j = ((row >> 3) * 256) + n0 + (row & 7);
        int c = k >> 3;
        *(__nv_bfloat16*)(smW + row * 512 + ((c ^ (row & 7)) * 16) + (k & 7) * 2) =
            __float2bfloat16(Wh[(size_t)j * H_ + k]);
    }
    {
        uint4 z = make_uint4(0, 0, 0, 0);
        for (int i = t; i < 2048; i += 128) ((uint4*)smA)[i] = z;
    }
    __syncthreads();

    const u32 smA_b = smem_u32(smA), smW_b = smem_u32(smW);
    const int qbl = w * 16 + (l >> 2);       // local b (and +8)
    const int u0  = 2 * (l & 3);

    float cst[4];
#pragma unroll
    for (int u = 0; u < 4; u++) cst[u] = 0.f;

    const __nv_bfloat16* Gd = g_Gb + (size_t)d * S_ * B_ * G4_;
    __nv_bfloat16*       Hd = g_hb + (size_t)d * S_ * B_ * H_;

    u32 gq[8], gqn[8];
    {
        const __nv_bfloat16* Gp = Gd + (size_t)(d ? S_ - 1 : 0) * B_ * G4_;
#pragma unroll
        for (int i = 0; i < 2; i++) {
            int b = bh * 64 + qbl + 8 * i;
#pragma unroll
            for (int gg = 0; gg < 4; gg++)
                gqn[i * 4 + gg] = *(const u32*)(Gp + (size_t)b * G4_ + gg * 256 + n0 + u0);
        }
    }

    for (int step = 0; step < S_; step++) {
        const int s = d ? (S_ - 1 - step) : step;

#pragma unroll
        for (int j = 0; j < 8; j++) gq[j] = gqn[j];
        if (step + 1 < S_) {
            const int sn = d ? (S_ - 2 - step) : (step + 1);
            const __nv_bfloat16* Gp = Gd + (size_t)sn * B_ * G4_;
#pragma unroll
            for (int i = 0; i < 2; i++) {
                int b = bh * 64 + qbl + 8 * i;
#pragma unroll
                for (int gg = 0; gg < 4; gg++)
                    gqn[i * 4 + gg] = *(const u32*)(Gp + (size_t)b * G4_ + gg * 256 + n0 + u0);
            }
        }

        if (step > 0) {
            const char* hsrc = (const char*)(Hd + ((size_t)(d ? s + 1 : s - 1) * B_ + bh * 64) * H_);
            for (int i = t; i < 1024; i += 128) {
                int row = i >> 4, c = i & 15;
                cp16(smA + row * 512 + ((c ^ (row & 7)) * 16), hsrc + row * 512 + c * 16);
            }
            CP_COMMIT();
            for (int i = t; i < 1024; i += 128) {
                int row = i >> 4, c = (i & 15) + 16;
                cp16(smA + row * 512 + ((c ^ (row & 7)) * 16), hsrc + row * 512 + c * 16);
            }
            CP_COMMIT();
        }

        float acc[4][4];
#pragma unroll
        for (int g = 0; g < 4; g++)
#pragma unroll
            for (int q = 0; q < 4; q++) acc[g][q] = 0.f;

        CP_WAIT1();
        __syncthreads();
#pragma unroll
        for (int kk = 0; kk < 8; kk++) {
            u32 a0r, a1r, a2r, a3r;
            {
                int row = w * 16 + (l & 15);
                int c = kk * 2 + (l >> 4);
                ldsm4(a0r, a1r, a2r, a3r, smA_b + row * 512 + ((c ^ (row & 7)) * 16));
            }
#pragma unroll
            for (int g = 0; g < 4; g++) {
                int row = g * 8 + (l & 7);
                int c = kk * 2 + ((l >> 3) & 1);
                u32 b0, b1;
                ldsm2(b0, b1, smW_b + row * 512 + ((c ^ (row & 7)) * 16));
                hmma(acc[g], a0r, a1r, a2r, a3r, b0, b1);
            }
        }
        CP_WAIT0();
        __syncthreads();
#pragma unroll
        for (int kk = 8; kk < 16; kk++) {
            u32 a0r, a1r, a2r, a3r;
            {
                int row = w * 16 + (l & 15);
                int c = kk * 2 + (l >> 4);
                ldsm4(a0r, a1r, a2r, a3r, smA_b + row * 512 + ((c ^ (row & 7)) * 16));
            }
#pragma unroll
            for (int g = 0; g < 4; g++) {
                int row = g * 8 + (l & 7);
                int c = kk * 2 + ((l >> 3) & 1);
                u32 b0, b1;
                ldsm2(b0, b1, smW_b + row * 512 + ((c ^ (row & 7)) * 16));
                hmma(acc[g], a0r, a1r, a2r, a3r, b0, b1);
            }
        }

        // combine + store h (MUFU-free activations)
#pragma unroll
        for (int i = 0; i < 2; i++) {
            const int bl = qbl + 8 * i;
            const int e = 2 * i;
            float2 gi = __bfloat1622float2(*(const __nv_bfloat162*)&gq[i * 4 + 0]);
            float2 gf = __bfloat1622float2(*(const __nv_bfloat162*)&gq[i * 4 + 1]);
            float2 gg = __bfloat1622float2(*(const __nv_bfloat162*)&gq[i * 4 + 2]);
            float2 go = __bfloat1622float2(*(const __nv_bfloat162*)&gq[i * 4 + 3]);
            const int ci = 2 * i;
            float c0 = fsig(acc[1][e] + gf.x) * cst[ci]
                     + fsig(acc[0][e] + gi.x) * ftanh(acc[2][e] + gg.x);
            cst[ci] = c0;
            float h0 = fsig(acc[3][e] + go.x) * ftanh(c0);
            float c1 = fsig(acc[1][e + 1] + gf.y) * cst[ci + 1]
                     + fsig(acc[0][e + 1] + gi.y) * ftanh(acc[2][e + 1] + gg.y);
            cst[ci + 1] = c1;
            float h1 = fsig(acc[3][e + 1] + go.y) * ftanh(c1);
            *(u32*)(Hd + ((size_t)s * B_ + bh * 64 + bl) * H_ + n0 + u0) = bfpack(h0, h1);
        }

        // monotonic-counter grid barrier (group of 32 CTAs)
        if (step != S_ - 1) {
            __syncthreads();
            if (t == 0) {
                atom_add_rel(&g_barcnt[grp], 1);
                const u32 tgt = (u32)(32 * (step + 1));
                while ((int)(ld_acq(&g_barcnt[grp]) - tgt) < 0) { __nanosleep(20); }
            }
            __syncthreads();
        }
    }
}

// ---------------------------------------------------------------------------
// K3: emissions via mma.sync. grid 512 (s), block 128.
// ---------------------------------------------------------------------------
__global__ void __launch_bounds__(128) k_emis(const float* __restrict__ bo)
{
    extern __shared__ __align__(16) char smraw[];
    char* sm = smraw + ((1024 - (smem_u32(smraw) & 1023)) & 1023);
    char* smW  = sm;
    char* smA0 = sm + 65536;
    char* smA1 = sm + 131072;
    float* bsm = (float*)(sm + 196608);

    const int s = blockIdx.x;
    const int t = threadIdx.x;
    const int l = t & 31, w = t >> 5;

    if (t < 64) bsm[t] = (t < T_) ? bo[t] : 0.f;

    for (int i = t; i < 4096; i += 128) {
        int row = i >> 6, c = i & 63;
        cp16(smW + row * 1024 + ((c ^ (row & 7)) * 16),
             (const char*)g_woutb + row * 1024 + c * 16);
    }
    CP_COMMIT();
    for (int i = t; i < 4096; i += 128) {
        int row = i >> 5, c = i & 31;
        cp16(smA0 + row * 512 + ((c ^ (row & 7)) * 16),
             (const char*)(g_hb + ((size_t)s * B_ + row) * H_) + c * 16);
    }
    CP_COMMIT();
    for (int i = t; i < 4096; i += 128) {
        int row = i >> 5, c = i & 31;
        cp16(smA1 + row * 512 + ((c ^ (row & 7)) * 16),
             (const char*)(g_hb + (size_t)S_ * B_ * H_ + ((size_t)s * B_ + row) * H_) + c * 16);
    }
    CP_COMMIT();

    const u32 smW_b = smem_u32(smW);

    float acc[2][8][4];
#pragma unroll
    for (int m = 0; m < 2; m++)
#pragma unroll
        for (int n = 0; n < 8; n++)
#pragma unroll
            for (int q = 0; q < 4; q++) acc[m][n][q] = 0.f;

    auto stage = [&](u32 smA_b, int wc0) {
#pragma unroll 4
        for (int kk = 0; kk < 16; kk++) {
            u32 a[2][4];
#pragma unroll
            for (int m = 0; m < 2; m++) {
                int row = w * 32 + m * 16 + (l & 15);
                int c = kk * 2 + (l >> 4);
                ldsm4(a[m][0], a[m][1], a[m][2], a[m][3],
                      smA_b + row * 512 + ((c ^ (row & 7)) * 16));
            }
#pragma unroll
            for (int nt = 0; nt < 8; nt++) {
                int row = nt * 8 + (l & 7);
                int c = wc0 + kk * 2 + ((l >> 3) & 1);
                u32 b0, b1;
                ldsm2(b0, b1, smW_b + row * 1024 + ((c ^ (row & 7)) * 16));
#pragma unroll
                for (int m = 0; m < 2; m++)
                    hmma(acc[m][nt], a[m][0], a[m][1], a[m][2], a[m][3], b0, b1);
            }
        }
    };

    CP_WAIT1();
    __syncthreads();
    stage(smem_u32(smA0), 0);
    CP_WAIT0();
    __syncthreads();
    stage(smem_u32(smA1), 32);

#pragma unroll
    for (int m = 0; m < 2; m++)
#pragma unroll
    for (int nt = 0; nt < 8; nt++) {
        int r  = w * 32 + m * 16 + (l >> 2);
        int jl = nt * 8 + 2 * (l & 3);
        if (jl < T_) {
            float b0 = bsm[jl], b1 = bsm[jl + 1];
            *(float2*)(g_emis + ((size_t)s * B_ + r) * T_ + jl)     = make_float2(acc[m][nt][0] + b0, acc[m][nt][1] + b1);
            *(float2*)(g_emis + ((size_t)s * B_ + r + 8) * T_ + jl) = make_float2(acc[m][nt][2] + b0, acc[m][nt][3] + b1);
        }
    }
}

// ---------------------------------------------------------------------------
// K4: CRF — one warp per batch element, 128 CTAs.
// ---------------------------------------------------------------------------
__global__ void __launch_bounds__(32) k_crf(
    const float* __restrict__ trans, const float* __restrict__ start_t,
    const float* __restrict__ end_t, const int* __restrict__ tags)
{
    __shared__ __align__(16) u64 Esp[T_ * 32];
    __shared__ float pw[64];

    const int b = blockIdx.x;
    const int l = threadIdx.x;

    for (int i = l; i < T_ * 32; i += 32) {
        int tt = i >> 5, c = i & 31;
        float e0 = expf(trans[tt * T_ + c]);
        float e1 = (c + 32 < T_) ? expf(trans[tt * T_ + c + 32]) : 0.f;
        Esp[i] = pk2(e0, e1);
    }
    __syncwarp();

    const bool v1 = (l + 32 < T_);
    float a0 = start_t[l] + g_emis[(size_t)b * T_ + l];
    float a1 = v1 ? (start_t[l + 32] + g_emis[(size_t)b * T_ + l + 32]) : -1e30f;

    float e0n = g_emis[((size_t)B_ + b) * T_ + l];
    float e1n = v1 ? g_emis[((size_t)B_ + b) * T_ + l + 32] : 0.f;

    for (int s = 1; s < S_; s++) {
        float e0 = e0n, e1 = e1n;
        if (s + 1 < S_) {
            const float* es = g_emis + ((size_t)(s + 1) * B_ + b) * T_;
            e0n = es[l];
            e1n = v1 ? es[l + 32] : 0.f;
        }

        float m = __shfl_sync(0xffffffffu, a0, 0);
        pw[l]      = __expf(a0 - m);
        pw[l + 32] = v1 ? __expf(a1 - m) : 0.f;
        __syncwarp();

        u64 q0 = 0ull, q1 = 0ull, q2 = 0ull, q3 = 0ull;
#pragma unroll
        for (int tt = 0; tt < 48; tt += 4) {
            q0 = f2ma(pk2(pw[tt],     pw[tt]),     Esp[(tt)     * 32 + l], q0);
            q1 = f2ma(pk2(pw[tt + 1], pw[tt + 1]), Esp[(tt + 1) * 32 + l], q1);
            q2 = f2ma(pk2(pw[tt + 2], pw[tt + 2]), Esp[(tt + 2) * 32 + l], q2);
            q3 = f2ma(pk2(pw[tt + 3], pw[tt + 3]), Esp[(tt + 3) * 32 + l], q3);
        }
        q0 = f2ma(pk2(pw[48], pw[48]), Esp[48 * 32 + l], q0);
        q1 = f2ma(pk2(pw[49], pw[49]), Esp[49 * 32 + l], q1);
        float2 qf = upk(f2add(f2add(q0, q1), f2add(q2, q3)));
        a0 = m + __logf(qf.x) + e0;
        a1 = v1 ? (m + __logf(qf.y) + e1) : -1e30f;
        __syncwarp();
    }

    float vv0 = a0 + end_t[l];
    float vv1 = v1 ? (a1 + end_t[l + 32]) : -1e30f;
    float m = fmaxf(vv0, vv1);
#pragma unroll
    for (int o = 16; o; o >>= 1) m = fmaxf(m, __shfl_xor_sync(0xffffffffu, m, o));
    float e = __expf(vv0 - m) + (v1 ? __expf(vv1 - m) : 0.f);
#pragma unroll
    for (int o = 16; o; o >>= 1) e += __shfl_xor_sync(0xffffffffu, e, o);
    float logZ = m + __logf(e);

    float acc = 0.f;
    for (int s = 1 + l; s < S_; s += 32) {
        int tp = tags[b * S_ + s - 1];
        int tc = tags[b * S_ + s];
        acc += trans[tp * T_ + tc] + g_emis[((size_t)s * B_ + b) * T_ + tc];
    }
#pragma unroll
    for (int o = 16; o; o >>= 1) acc += __shfl_xor_sync(0xffffffffu, acc, o);

    if (l == 0) {
        int t0 = tags[b * S_];
        int tl = tags[b * S_ + S_ - 1];
        g_res[b] = logZ - (start_t[t0] + g_emis[(size_t)b * T_ + t0] + acc + end_t[tl]);
    }
}

// ---------------------------------------------------------------------------
// K5: final mean
// ---------------------------------------------------------------------------
__global__ void k_final(float* __restrict__ out)
{
    __shared__ float red[4];
    int t = threadIdx.x;
    float v = g_res[t];
#pragma unroll
    for (int o = 16; o; o >>= 1) v += __shfl_xor_sync(0xffffffffu, v, o);
    if ((t & 31) == 0) red[t >> 5] = v;
    __syncthreads();
    if (t == 0) out[0] = (red[0] + red[1] + red[2] + red[3]) * (1.f / (float)B_);
}

// ---------------------------------------------------------------------------
// Launch
// ---------------------------------------------------------------------------
extern "C" void kernel_launch(void* const* d_in, const int* in_sizes, int n_in,
                              void* d_out, int out_size)
{
    const int*   sent  = (const int*)  d_in[0];
    const int*   tags  = (const int*)  d_in[1];
    const float* emb   = (const float*)d_in[3];
    const float* wih_f = (const float*)d_in[4];
    const float* whh_f = (const float*)d_in[5];
    const float* bih_f = (const float*)d_in[6];
    const float* bhh_f = (const float*)d_in[7];
    const float* wih_b = (const float*)d_in[8];
    const float* whh_b = (const float*)d_in[9];
    const float* bih_b = (const float*)d_in[10];
    const float* bhh_b = (const float*)d_in[11];
    const float* Wout  = (const float*)d_in[12];
    const float* bout  = (const float*)d_in[13];
    const float* strt  = (const float*)d_in[14];
    const float* endt  = (const float*)d_in[15];
    const float* trans = (const float*)d_in[16];
    float* out = (float*)d_out;

    const int input_smem = 199168;
    const int lstm_smem  = 50176;
    const int emis_smem  = 197888;
    cudaFuncSetAttribute(k_input, cudaFuncAttributeMaxDynamicSharedMemorySize, input_smem);
    cudaFuncSetAttribute(k_lstm,  cudaFuncAttributeMaxDynamicSharedMemorySize, lstm_smem);
    cudaFuncSetAttribute(k_emis,  cudaFuncAttributeMaxDynamicSharedMemorySize, emis_smem);

    int nconv = (EMB2 + 2 * WIH2 + WOUT2 + 255) / 256;
    k_convert<<<nconv, 256>>>(emb, wih_f, wih_b, Wout);
    k_input<<<dim3(8, 2, 256), 256, input_smem>>>(sent, bih_f, bhh_f, bih_b, bhh_b);
    k_lstm<<<128, 128, lstm_smem>>>(whh_f, whh_b);
    k_emis<<<512, 128, emis_smem>>>(bout);
    k_crf<<<128, 32>>>(trans, strt, endt, tags);
    k_final<<<1, 128>>>(out);
}

// round 13
// speedup vs baseline: 1.1024x; 1.0526x over previous
#include <cuda_runtime.h>
#include <cuda_bf16.h>
#include <math.h>

#define V_   50000
#define E_   256
#define H_   256
#define G4_  1024
#define HD_  512
#define T_   50
#define B_   128
#define S_   512

typedef unsigned long long u64;
typedef unsigned int u32;

// ---------------------------------------------------------------------------
// Device scratch
// ---------------------------------------------------------------------------
__device__ __nv_bfloat16 g_embb[(size_t)V_ * E_];
__device__ __nv_bfloat16 g_wihb[(size_t)2 * G4_ * E_];
__device__ __nv_bfloat16 g_woutb[(size_t)64 * HD_];        // padded [64][512]
__device__ __nv_bfloat16 g_Gb[(size_t)2 * S_ * B_ * G4_];  // [d][s][b][j]
__device__ __nv_bfloat16 g_hb[(size_t)2 * S_ * B_ * H_];   // [d][s][b][k]
__device__ __align__(16) float g_emis[(size_t)S_ * B_ * T_];
__device__ float g_res[B_];
__device__ u32 g_barcnt[4];     // monotonic arrival counters; zeroed by k_convert

// ---------------------------------------------------------------------------
// Helpers
// ---------------------------------------------------------------------------
__device__ __forceinline__ u64 pk2(float lo, float hi) {
    u64 r; asm("mov.b64 %0, {%1, %2};" : "=l"(r) : "f"(lo), "f"(hi)); return r;
}
__device__ __forceinline__ u64 f2ma(u64 a, u64 b, u64 c) {
    u64 d; asm("fma.rn.f32x2 %0, %1, %2, %3;" : "=l"(d) : "l"(a), "l"(b), "l"(c)); return d;
}
__device__ __forceinline__ u64 f2add(u64 a, u64 b) {
    u64 d; asm("add.rn.f32x2 %0, %1, %2;" : "=l"(d) : "l"(a), "l"(b)); return d;
}
__device__ __forceinline__ float2 upk(u64 v) {
    float2 f; asm("mov.b64 {%0, %1}, %2;" : "=f"(f.x), "=f"(f.y) : "l"(v)); return f;
}
__device__ __forceinline__ u32 smem_u32(const void* p) { return (u32)__cvta_generic_to_shared(p); }
__device__ __forceinline__ void cp16(void* smem, const void* g) {
    asm volatile("cp.async.cg.shared.global [%0], [%1], 16;" :: "r"(smem_u32(smem)), "l"(g));
}
#define CP_COMMIT() asm volatile("cp.async.commit_group;")
#define CP_WAITN(n) asm volatile("cp.async.wait_group %0;" :: "n"(n))

__device__ __forceinline__ u32 bfpack(float lo, float hi) {
    u32 r; asm("cvt.rn.bf16x2.f32 %0, %1, %2;" : "=r"(r) : "f"(hi), "f"(lo)); return r;
}
__device__ __forceinline__ float tanhx(float x) {
    float r; asm("tanh.approx.f32 %0, %1;" : "=f"(r) : "f"(x)); return r;
}
__device__ __forceinline__ float sigx(float x) { return 0.5f * tanhx(0.5f * x) + 0.5f; }

__device__ __forceinline__ void ldsm4(u32& r0, u32& r1, u32& r2, u32& r3, u32 addr) {
    asm volatile("ldmatrix.sync.aligned.m8n8.x4.shared.b16 {%0,%1,%2,%3}, [%4];"
                 : "=r"(r0), "=r"(r1), "=r"(r2), "=r"(r3) : "r"(addr));
}
__device__ __forceinline__ void ldsm2(u32& r0, u32& r1, u32 addr) {
    asm volatile("ldmatrix.sync.aligned.m8n8.x2.shared.b16 {%0,%1}, [%2];"
                 : "=r"(r0), "=r"(r1) : "r"(addr));
}
__device__ __forceinline__ void hmma(float* d, u32 a0, u32 a1, u32 a2, u32 a3, u32 b0, u32 b1) {
    asm volatile(
        "mma.sync.aligned.m16n8k16.row.col.f32.bf16.bf16.f32 "
        "{%0,%1,%2,%3}, {%4,%5,%6,%7}, {%8,%9}, {%0,%1,%2,%3};"
        : "+f"(d[0]), "+f"(d[1]), "+f"(d[2]), "+f"(d[3])
        : "r"(a0), "r"(a1), "r"(a2), "r"(a3), "r"(b0), "r"(b1));
}

__device__ __forceinline__ u32 ld_acq(const u32* p) {
    u32 v; asm volatile("ld.acquire.gpu.u32 %0, [%1];" : "=r"(v) : "l"(p) : "memory"); return v;
}
__device__ __forceinline__ u32 atom_add_rel(u32* p, u32 v) {
    u32 o; asm volatile("atom.release.gpu.add.u32 %0, [%1], %2;" : "=r"(o) : "l"(p), "r"(v) : "memory"); return o;
}

// ---------------------------------------------------------------------------
// K0: convert emb + W_ih + W_out(padded to 64 rows) to bf16; reset barriers
// ---------------------------------------------------------------------------
#define EMB2  ((V_ * E_) / 2)
#define WIH2  ((G4_ * E_) / 2)
#define WOUT2 ((64 * HD_) / 2)
__global__ void __launch_bounds__(256) k_convert(
    const float* __restrict__ emb, const float* __restrict__ wf,
    const float* __restrict__ wb,  const float* __restrict__ wo)
{
    if (blockIdx.x == 0 && threadIdx.x < 4) g_barcnt[threadIdx.x] = 0;  // ordered before k_lstm (same stream)
    int i = blockIdx.x * 256 + threadIdx.x;
    if (i >= EMB2 + 2 * WIH2 + WOUT2) return;
    float2 v; __nv_bfloat162* dst;
    if (i < EMB2)                 { v = ((const float2*)emb)[i];              dst = (__nv_bfloat162*)g_embb + i; }
    else if (i < EMB2 + WIH2)     { v = ((const float2*)wf)[i - EMB2];        dst = (__nv_bfloat162*)g_wihb + (i - EMB2); }
    else if (i < EMB2 + 2 * WIH2) { v = ((const float2*)wb)[i - EMB2 - WIH2]; dst = (__nv_bfloat162*)g_wihb + (i - EMB2); }
    else {
        int j = i - EMB2 - 2 * WIH2;
        int tag = (j * 2) >> 9, k = (j * 2) & 511;
        v.x = (tag < T_) ? wo[(size_t)tag * HD_ + k] : 0.f;
        v.y = (tag < T_) ? wo[(size_t)tag * HD_ + k + 1] : 0.f;
        dst = (__nv_bfloat162*)g_woutb + j;
    }
    *dst = __floats2bfloat162_rn(v.x, v.y);
}

// ---------------------------------------------------------------------------
// K1: input projection via mma.sync bf16. grid (8 jt, 2 d, 256 sp), block 256.
// ---------------------------------------------------------------------------
__global__ void __launch_bounds__(256) k_input(
    const int* __restrict__ sent,
    const float* __restrict__ bih_f, const float* __restrict__ bhh_f,
    const float* __restrict__ bih_b, const float* __restrict__ bhh_b)
{
    extern __shared__ __align__(16) char smraw[];
    char* sm = smraw + ((1024 - (smem_u32(smraw) & 1023)) & 1023);
    char* smB  = sm;
    char* smA0 = sm + 65536;
    char* smA1 = sm + 131072;
    int*  toks0 = (int*)(sm + 196608);
    int*  toks1 = (int*)(sm + 197120);
    float* bsm  = (float*)(sm + 197632);

    const int jt = blockIdx.x, d = blockIdx.y, sp = blockIdx.z;
    const int s0 = 2 * sp, s1 = 2 * sp + 1;
    const int j0 = jt * 128;
    const int t = threadIdx.x;
    const int l = t & 31, w = t >> 5;
    const int wm = w & 3, wn = w >> 2;

    if (t < 128) {
        toks0[t] = sent[t * S_ + s0];
        toks1[t] = sent[t * S_ + s1];
        const float* bi = d ? bih_b : bih_f;
        const float* bh = d ? bhh_b : bhh_f;
        bsm[t] = bi[j0 + t] + bh[j0 + t];
    }
    __syncthreads();

    for (int i = t; i < 4096; i += 256) {
        int row = i >> 5, c = i & 31;
        cp16(smB + row * 512 + ((c ^ (row & 7)) * 16),
             (const char*)(g_wihb + ((size_t)d * G4_ + j0 + row) * E_) + c * 16);
    }
    CP_COMMIT();
    for (int i = t; i < 4096; i += 256) {
        int row = i >> 5, c = i & 31;
        cp16(smA0 + row * 512 + ((c ^ (row & 7)) * 16),
             (const char*)(g_embb + (size_t)toks0[row] * E_) + c * 16);
    }
    CP_COMMIT();
    for (int i = t; i < 4096; i += 256) {
        int row = i >> 5, c = i & 31;
        cp16(smA1 + row * 512 + ((c ^ (row & 7)) * 16),
             (const char*)(g_embb + (size_t)toks1[row] * E_) + c * 16);
    }
    CP_COMMIT();

    const u32 smB_b = smem_u32(smB);

    auto tile = [&](u32 smA_b, int s) {
        float acc[2][8][4];
#pragma unroll
        for (int m = 0; m < 2; m++)
#pragma unroll
            for (int n = 0; n < 8; n++)
#pragma unroll
                for (int q = 0; q < 4; q++) acc[m][n][q] = 0.f;

#pragma unroll 4
        for (int kk = 0; kk < 16; kk++) {
            u32 a[2][4];
#pragma unroll
            for (int m = 0; m < 2; m++) {
                int row = wm * 32 + m * 16 + (l & 15);
                int c = kk * 2 + (l >> 4);
                ldsm4(a[m][0], a[m][1], a[m][2], a[m][3],
                      smA_b + row * 512 + ((c ^ (row & 7)) * 16));
            }
#pragma unroll
            for (int nt = 0; nt < 8; nt++) {
                int row = wn * 64 + nt * 8 + (l & 7);
                int c = kk * 2 + ((l >> 3) & 1);
                u32 b0, b1;
                ldsm2(b0, b1, smB_b + row * 512 + ((c ^ (row & 7)) * 16));
#pragma unroll
                for (int m = 0; m < 2; m++)
                    hmma(acc[m][nt], a[m][0], a[m][1], a[m][2], a[m][3], b0, b1);
            }
        }

        __nv_bfloat16* Gbase = g_Gb + ((size_t)(d * S_ + s) * B_) * G4_;
#pragma unroll
        for (int m = 0; m < 2; m++)
#pragma unroll
        for (int nt = 0; nt < 8; nt++) {
            int r  = wm * 32 + m * 16 + (l >> 2);
            int jl = wn * 64 + nt * 8 + 2 * (l & 3);
            float b0 = bsm[jl], b1 = bsm[jl + 1];
            *(u32*)(Gbase + (size_t)r * G4_ + j0 + jl)       = bfpack(acc[m][nt][0] + b0, acc[m][nt][1] + b1);
            *(u32*)(Gbase + (size_t)(r + 8) * G4_ + j0 + jl) = bfpack(acc[m][nt][2] + b0, acc[m][nt][3] + b1);
        }
    };

    CP_WAITN(1);
    __syncthreads();
    tile(smem_u32(smA0), s0);
    CP_WAITN(0);
    __syncthreads();
    tile(smem_u32(smA1), s1);
}

// ---------------------------------------------------------------------------
// K2: persistent bidirectional LSTM (R10 structure). grid 128, block 128.
// CTA = (d = cta>>6, bhalf = (cta>>5)&1, slice = cta&31). M=64, N=32, K=256.
// 4 independent groups of 32 CTAs; monotonic-counter barrier (tight spin).
// h staging in 4 cp.async chunks interleaved with 4 MMA chunks; next-step
// G prefetch hoisted above the barrier to ride under the wait.
// ---------------------------------------------------------------------------
__global__ void __launch_bounds__(128, 1) k_lstm(
    const float* __restrict__ whh_f, const float* __restrict__ whh_b)
{
    extern __shared__ __align__(16) char smraw[];
    char* sm = smraw + ((1024 - (smem_u32(smraw) & 1023)) & 1023);
    char* smA = sm;                  // 32KB h tile [64 b][512B]
    char* smW = sm + 32768;          // 16KB W_hh slice [32][256] bf16

    const int cta   = blockIdx.x;
    const int d     = cta >> 6;
    const int bh    = (cta >> 5) & 1;
    const int slice = cta & 31;
    const int n0    = slice * 8;
    const int grp   = cta >> 5;      // 0..3
    const int t     = threadIdx.x;
    const int l = t & 31, w = t >> 5;
    const float* __restrict__ Wh = d ? whh_b : whh_f;

    for (int i = t; i < 8192; i += 128) {
        int row = i >> 8, k = i & 255;
        int j = ((row >> 3) * 256) + n0 + (row & 7);
        int c = k >> 3;
        *(__nv_bfloat16*)(smW + row * 512 + ((c ^ (row & 7)) * 16) + (k & 7) * 2) =
            __float2bfloat16(Wh[(size_t)j * H_ + k]);
    }
    {
        uint4 z = make_uint4(0, 0, 0, 0);
        for (int i = t; i < 2048; i += 128) ((uint4*)smA)[i] = z;
    }
    __syncthreads();

    const u32 smA_b = smem_u32(smA), smW_b = smem_u32(smW);
    const int qbl = w * 16 + (l >> 2);       // local b (and +8)
    const int u0  = 2 * (l & 3);

    float cst[4];
#pragma unroll
    for (int u = 0; u < 4; u++) cst[u] = 0.f;

    const __nv_bfloat16* Gd = g_Gb + (size_t)d * S_ * B_ * G4_;
    __nv_bfloat16*       Hd = g_hb + (size_t)d * S_ * B_ * H_;

    u32 gq[8], gqn[8];
    {
        const __nv_bfloat16* Gp = Gd + (size_t)(d ? S_ - 1 : 0) * B_ * G4_;
#pragma unroll
        for (int i = 0; i < 2; i++) {
            int b = bh * 64 + qbl + 8 * i;
#pragma unroll
            for (int gg = 0; gg < 4; gg++)
                gqn[i * 4 + gg] = *(const u32*)(Gp + (size_t)b * G4_ + gg * 256 + n0 + u0);
        }
    }

    // one MMA k-chunk: kk in [kk0, kk0+4)
    auto mma_chunk = [&](int kk0, float (*acc)[4]) {
#pragma unroll
        for (int kk = kk0; kk < kk0 + 4; kk++) {
            u32 a0r, a1r, a2r, a3r;
            {
                int row = w * 16 + (l & 15);
                int c = kk * 2 + (l >> 4);
                ldsm4(a0r, a1r, a2r, a3r, smA_b + row * 512 + ((c ^ (row & 7)) * 16));
            }
#pragma unroll
            for (int g = 0; g < 4; g++) {
                int row = g * 8 + (l & 7);
                int c = kk * 2 + ((l >> 3) & 1);
                u32 b0, b1;
                ldsm2(b0, b1, smW_b + row * 512 + ((c ^ (row & 7)) * 16));
                hmma(acc[g], a0r, a1r, a2r, a3r, b0, b1);
            }
        }
    };

    for (int step = 0; step < S_; step++) {
        const int s = d ? (S_ - 1 - step) : step;

#pragma unroll
        for (int j = 0; j < 8; j++) gq[j] = gqn[j];

        if (step > 0) {
            const char* hsrc = (const char*)(Hd + ((size_t)(d ? s + 1 : s - 1) * B_ + bh * 64) * H_);
            // 4 chunks of 8KB: chunk i covers 16B-columns [8i, 8i+8)
#pragma unroll
            for (int ch = 0; ch < 4; ch++) {
                for (int i = t; i < 512; i += 128) {
                    int row = i >> 3, c = (i & 7) + ch * 8;
                    cp16(smA + row * 512 + ((c ^ (row & 7)) * 16), hsrc + row * 512 + c * 16);
                }
                CP_COMMIT();
            }
        }

        float acc[4][4];
#pragma unroll
        for (int g = 0; g < 4; g++)
#pragma unroll
            for (int q = 0; q < 4; q++) acc[g][q] = 0.f;

        if (step > 0) {
            CP_WAITN(3); __syncthreads();
            mma_chunk(0, acc);
            CP_WAITN(2); __syncthreads();
            mma_chunk(4, acc);
            CP_WAITN(1); __syncthreads();
            mma_chunk(8, acc);
            CP_WAITN(0); __syncthreads();
            mma_chunk(12, acc);
        }
        // step 0: h_prev = 0, acc stays 0

        // combine + store h
#pragma unroll
        for (int i = 0; i < 2; i++) {
            const int bl = qbl + 8 * i;
            const int e = 2 * i;
            float2 gi = __bfloat1622float2(*(const __nv_bfloat162*)&gq[i * 4 + 0]);
            float2 gf = __bfloat1622float2(*(const __nv_bfloat162*)&gq[i * 4 + 1]);
            float2 gg = __bfloat1622float2(*(const __nv_bfloat162*)&gq[i * 4 + 2]);
            float2 go = __bfloat1622float2(*(const __nv_bfloat162*)&gq[i * 4 + 3]);
            const int ci = 2 * i;
            float c0 = sigx(acc[1][e] + gf.x) * cst[ci]
                     + sigx(acc[0][e] + gi.x) * tanhx(acc[2][e] + gg.x);
            cst[ci] = c0;
            float h0 = sigx(acc[3][e] + go.x) * tanhx(c0);
            float c1 = sigx(acc[1][e + 1] + gf.y) * cst[ci + 1]
                     + sigx(acc[0][e + 1] + gi.y) * tanhx(acc[2][e + 1] + gg.y);
            cst[ci + 1] = c1;
            float h1 = sigx(acc[3][e + 1] + go.y) * tanhx(c1);
            *(u32*)(Hd + ((size_t)s * B_ + bh * 64 + bl) * H_ + n0 + u0) = bfpack(h0, h1);
        }

        // next-step G prefetch BEFORE the barrier (independent of h; its DRAM
        // latency rides under the barrier wait)
        if (step + 1 < S_) {
            const int sn = d ? (S_ - 2 - step) : (step + 1);
            const __nv_bfloat16* Gp = Gd + (size_t)sn * B_ * G4_;
#pragma unroll
            for (int i = 0; i < 2; i++) {
                int b = bh * 64 + qbl + 8 * i;
#pragma unroll
                for (int gg = 0; gg < 4; gg++)
                    gqn[i * 4 + gg] = *(const u32*)(Gp + (size_t)b * G4_ + gg * 256 + n0 + u0);
            }
        }

        // monotonic-counter grid barrier (group of 32 CTAs), tight spin
        if (step != S_ - 1) {
            __syncthreads();
            if (t == 0) {
                atom_add_rel(&g_barcnt[grp], 1);
                const u32 tgt = (u32)(32 * (step + 1));
                while ((int)(ld_acq(&g_barcnt[grp]) - tgt) < 0) { }
            }
            __syncthreads();
        }
    }
}

// ---------------------------------------------------------------------------
// K3: emissions via mma.sync. grid 512 (s), block 128.
// ---------------------------------------------------------------------------
__global__ void __launch_bounds__(128) k_emis(const float* __restrict__ bo)
{
    extern __shared__ __align__(16) char smraw[];
    char* sm = smraw + ((1024 - (smem_u32(smraw) & 1023)) & 1023);
    char* smW  = sm;
    char* smA0 = sm + 65536;
    char* smA1 = sm + 131072;
    float* bsm = (float*)(sm + 196608);

    const int s = blockIdx.x;
    const int t = threadIdx.x;
    const int l = t & 31, w = t >> 5;

    if (t < 64) bsm[t] = (t < T_) ? bo[t] : 0.f;

    for (int i = t; i < 4096; i += 128) {
        int row = i >> 6, c = i & 63;
        cp16(smW + row * 1024 + ((c ^ (row & 7)) * 16),
             (const char*)g_woutb + row * 1024 + c * 16);
    }
    CP_COMMIT();
    for (int i = t; i < 4096; i += 128) {
        int row = i >> 5, c = i & 31;
        cp16(smA0 + row * 512 + ((c ^ (row & 7)) * 16),
             (const char*)(g_hb + ((size_t)s * B_ + row) * H_) + c * 16);
    }
    CP_COMMIT();
    for (int i = t; i < 4096; i += 128) {
        int row = i >> 5, c = i & 31;
        cp16(smA1 + row * 512 + ((c ^ (row & 7)) * 16),
             (const char*)(g_hb + (size_t)S_ * B_ * H_ + ((size_t)s * B_ + row) * H_) + c * 16);
    }
    CP_COMMIT();

    const u32 smW_b = smem_u32(smW);

    float acc[2][8][4];
#pragma unroll
    for (int m = 0; m < 2; m++)
#pragma unroll
        for (int n = 0; n < 8; n++)
#pragma unroll
            for (int q = 0; q < 4; q++) acc[m][n][q] = 0.f;

    auto stage = [&](u32 smA_b, int wc0) {
#pragma unroll 4
        for (int kk = 0; kk < 16; kk++) {
            u32 a[2][4];
#pragma unroll
            for (int m = 0; m < 2; m++) {
                int row = w * 32 + m * 16 + (l & 15);
                int c = kk * 2 + (l >> 4);
                ldsm4(a[m][0], a[m][1], a[m][2], a[m][3],
                      smA_b + row * 512 + ((c ^ (row & 7)) * 16));
            }
#pragma unroll
            for (int nt = 0; nt < 8; nt++) {
                int row = nt * 8 + (l & 7);
                int c = wc0 + kk * 2 + ((l >> 3) & 1);
                u32 b0, b1;
                ldsm2(b0, b1, smW_b + row * 1024 + ((c ^ (row & 7)) * 16));
#pragma unroll
                for (int m = 0; m < 2; m++)
                    hmma(acc[m][nt], a[m][0], a[m][1], a[m][2], a[m][3], b0, b1);
            }
        }
    };

    CP_WAITN(1);
    __syncthreads();
    stage(smem_u32(smA0), 0);
    CP_WAITN(0);
    __syncthreads();
    stage(smem_u32(smA1), 32);

#pragma unroll
    for (int m = 0; m < 2; m++)
#pragma unroll
    for (int nt = 0; nt < 8; nt++) {
        int r  = w * 32 + m * 16 + (l >> 2);
        int jl = nt * 8 + 2 * (l & 3);
        if (jl < T_) {
            float b0 = bsm[jl], b1 = bsm[jl + 1];
            *(float2*)(g_emis + ((size_t)s * B_ + r) * T_ + jl)     = make_float2(acc[m][nt][0] + b0, acc[m][nt][1] + b1);
            *(float2*)(g_emis + ((size_t)s * B_ + r + 8) * T_ + jl) = make_float2(acc[m][nt][2] + b0, acc[m][nt][3] + b1);
        }
    }
}

// ---------------------------------------------------------------------------
// K4: CRF — one warp per batch element, 128 CTAs.
// ---------------------------------------------------------------------------
__global__ void __launch_bounds__(32) k_crf(
    const float* __restrict__ trans, const float* __restrict__ start_t,
    const float* __restrict__ end_t, const int* __restrict__ tags)
{
    __shared__ __align__(16) u64 Esp[T_ * 32];
    __shared__ float pw[64];

    const int b = blockIdx.x;
    const int l = threadIdx.x;

    for (int i = l; i < T_ * 32; i += 32) {
        int tt = i >> 5, c = i & 31;
        float e0 = expf(trans[tt * T_ + c]);
        float e1 = (c + 32 < T_) ? expf(trans[tt * T_ + c + 32]) : 0.f;
        Esp[i] = pk2(e0, e1);
    }
    __syncwarp();

    const bool v1 = (l + 32 < T_);
    float a0 = start_t[l] + g_emis[(size_t)b * T_ + l];
    float a1 = v1 ? (start_t[l + 32] + g_emis[(size_t)b * T_ + l + 32]) : -1e30f;

    float e0n = g_emis[((size_t)B_ + b) * T_ + l];
    float e1n = v1 ? g_emis[((size_t)B_ + b) * T_ + l + 32] : 0.f;

    for (int s = 1; s < S_; s++) {
        float e0 = e0n, e1 = e1n;
        if (s + 1 < S_) {
            const float* es = g_emis + ((size_t)(s + 1) * B_ + b) * T_;
            e0n = es[l];
            e1n = v1 ? es[l + 32] : 0.f;
        }

        float m = __shfl_sync(0xffffffffu, a0, 0);
        pw[l]      = __expf(a0 - m);
        pw[l + 32] = v1 ? __expf(a1 - m) : 0.f;
        __syncwarp();

        u64 q0 = 0ull, q1 = 0ull, q2 = 0ull, q3 = 0ull;
#pragma unroll
        for (int tt = 0; tt < 48; tt += 4) {
            q0 = f2ma(pk2(pw[tt],     pw[tt]),     Esp[(tt)     * 32 + l], q0);
            q1 = f2ma(pk2(pw[tt + 1], pw[tt + 1]), Esp[(tt + 1) * 32 + l], q1);
            q2 = f2ma(pk2(pw[tt + 2], pw[tt + 2]), Esp[(tt + 2) * 32 + l], q2);
            q3 = f2ma(pk2(pw[tt + 3], pw[tt + 3]), Esp[(tt + 3) * 32 + l], q3);
        }
        q0 = f2ma(pk2(pw[48], pw[48]), Esp[48 * 32 + l], q0);
        q1 = f2ma(pk2(pw[49], pw[49]), Esp[49 * 32 + l], q1);
        float2 qf = upk(f2add(f2add(q0, q1), f2add(q2, q3)));
        a0 = m + __logf(qf.x) + e0;
        a1 = v1 ? (m + __logf(qf.y) + e1) : -1e30f;
        __syncwarp();
    }

    float vv0 = a0 + end_t[l];
    float vv1 = v1 ? (a1 + end_t[l + 32]) : -1e30f;
    float m = fmaxf(vv0, vv1);
#pragma unroll
    for (int o = 16; o; o >>= 1) m = fmaxf(m, __shfl_xor_sync(0xffffffffu, m, o));
    float e = __expf(vv0 - m) + (v1 ? __expf(vv1 - m) : 0.f);
#pragma unroll
    for (int o = 16; o; o >>= 1) e += __shfl_xor_sync(0xffffffffu, e, o);
    float logZ = m + __logf(e);

    float acc = 0.f;
    for (int s = 1 + l; s < S_; s += 32) {
        int tp = tags[b * S_ + s - 1];
        int tc = tags[b * S_ + s];
        acc += trans[tp * T_ + tc] + g_emis[((size_t)s * B_ + b) * T_ + tc];
    }
#pragma unroll
    for (int o = 16; o; o >>= 1) acc += __shfl_xor_sync(0xffffffffu, acc, o);

    if (l == 0) {
        int t0 = tags[b * S_];
        int tl = tags[b * S_ + S_ - 1];
        g_res[b] = logZ - (start_t[t0] + g_emis[(size_t)b * T_ + t0] + acc + end_t[tl]);
    }
}

// ---------------------------------------------------------------------------
// K5: final mean
// ---------------------------------------------------------------------------
__global__ void k_final(float* __restrict__ out)
{
    __shared__ float red[4];
    int t = threadIdx.x;
    float v = g_res[t];
#pragma unroll
    for (int o = 16; o; o >>= 1) v += __shfl_xor_sync(0xffffffffu, v, o);
    if ((t & 31) == 0) red[t >> 5] = v;
    __syncthreads();
    if (t == 0) out[0] = (red[0] + red[1] + red[2] + red[3]) * (1.f / (float)B_);
}

// ---------------------------------------------------------------------------
// Launch
// ---------------------------------------------------------------------------
extern "C" void kernel_launch(void* const* d_in, const int* in_sizes, int n_in,
                              void* d_out, int out_size)
{
    const int*   sent  = (const int*)  d_in[0];
    const int*   tags  = (const int*)  d_in[1];
    const float* emb   = (const float*)d_in[3];
    const float* wih_f = (const float*)d_in[4];
    const float* whh_f = (const float*)d_in[5];
    const float* bih_f = (const float*)d_in[6];
    const float* bhh_f = (const float*)d_in[7];
    const float* wih_b = (const float*)d_in[8];
    const float* whh_b = (const float*)d_in[9];
    const float* bih_b = (const float*)d_in[10];
    const float* bhh_b = (const float*)d_in[11];
    const float* Wout  = (const float*)d_in[12];
    const float* bout  = (const float*)d_in[13];
    const float* strt  = (const float*)d_in[14];
    const float* endt  = (const float*)d_in[15];
    const float* trans = (const float*)d_in[16];
    float* out = (float*)d_out;

    const int input_smem = 199168;
    const int lstm_smem  = 50176;
    const int emis_smem  = 197888;
    cudaFuncSetAttribute(k_input, cudaFuncAttributeMaxDynamicSharedMemorySize, input_smem);
    cudaFuncSetAttribute(k_lstm,  cudaFuncAttributeMaxDynamicSharedMemorySize, lstm_smem);
    cudaFuncSetAttribute(k_emis,  cudaFuncAttributeMaxDynamicSharedMemorySize, emis_smem);

    int nconv = (EMB2 + 2 * WIH2 + WOUT2 + 255) / 256;
    k_convert<<<nconv, 256>>>(emb, wih_f, wih_b, Wout);
    k_input<<<dim3(8, 2, 256), 256, input_smem>>>(sent, bih_f, bhh_f, bih_b, bhh_b);
    k_lstm<<<128, 128, lstm_smem>>>(whh_f, whh_b);
    k_emis<<<512, 128, emis_smem>>>(bout);
    k_crf<<<128, 32>>>(trans, strt, endt, tags);
    k_final<<<1, 128>>>(out);
}

// round 14
// speedup vs baseline: 1.1026x; 1.0002x over previous
#include <cuda_runtime.h>
#include <cuda_bf16.h>
#include <math.h>

#define V_   50000
#define E_   256
#define H_   256
#define G4_  1024
#define HD_  512
#define T_   50
#define B_   128
#define S_   512

typedef unsigned long long u64;
typedef unsigned int u32;

// ---------------------------------------------------------------------------
// Device scratch
// ---------------------------------------------------------------------------
__device__ __nv_bfloat16 g_embb[(size_t)V_ * E_];
__device__ __nv_bfloat16 g_wihb[(size_t)2 * G4_ * E_];
__device__ __nv_bfloat16 g_woutb[(size_t)64 * HD_];        // padded [64][512]
__device__ __nv_bfloat16 g_Gb[(size_t)2 * S_ * B_ * G4_];  // [d][s][b][j]
__device__ __nv_bfloat16 g_hb[(size_t)2 * S_ * B_ * H_];   // [d][s][b][k]
__device__ __align__(16) float g_emis[(size_t)S_ * B_ * T_];
__device__ float g_res[B_];
__device__ u32 g_barcnt[4];     // monotonic arrival counters; zeroed by k_convert

// ---------------------------------------------------------------------------
// Helpers
// ---------------------------------------------------------------------------
__device__ __forceinline__ u64 pk2(float lo, float hi) {
    u64 r; asm("mov.b64 %0, {%1, %2};" : "=l"(r) : "f"(lo), "f"(hi)); return r;
}
__device__ __forceinline__ u64 f2ma(u64 a, u64 b, u64 c) {
    u64 d; asm("fma.rn.f32x2 %0, %1, %2, %3;" : "=l"(d) : "l"(a), "l"(b), "l"(c)); return d;
}
__device__ __forceinline__ u64 f2add(u64 a, u64 b) {
    u64 d; asm("add.rn.f32x2 %0, %1, %2;" : "=l"(d) : "l"(a), "l"(b)); return d;
}
__device__ __forceinline__ float2 upk(u64 v) {
    float2 f; asm("mov.b64 {%0, %1}, %2;" : "=f"(f.x), "=f"(f.y) : "l"(v)); return f;
}
__device__ __forceinline__ u32 smem_u32(const void* p) { return (u32)__cvta_generic_to_shared(p); }
__device__ __forceinline__ void cp16(void* smem, const void* g) {
    asm volatile("cp.async.cg.shared.global [%0], [%1], 16;" :: "r"(smem_u32(smem)), "l"(g));
}
#define CP_COMMIT() asm volatile("cp.async.commit_group;")
#define CP_WAITN(n) asm volatile("cp.async.wait_group %0;" :: "n"(n))

__device__ __forceinline__ u32 bfpack(float lo, float hi) {
    u32 r; asm("cvt.rn.bf16x2.f32 %0, %1, %2;" : "=r"(r) : "f"(hi), "f"(lo)); return r;
}
__device__ __forceinline__ float tanhx(float x) {
    float r; asm("tanh.approx.f32 %0, %1;" : "=f"(r) : "f"(x)); return r;
}
__device__ __forceinline__ float sigx(float x) { return 0.5f * tanhx(0.5f * x) + 0.5f; }

__device__ __forceinline__ void ldsm4(u32& r0, u32& r1, u32& r2, u32& r3, u32 addr) {
    asm volatile("ldmatrix.sync.aligned.m8n8.x4.shared.b16 {%0,%1,%2,%3}, [%4];"
                 : "=r"(r0), "=r"(r1), "=r"(r2), "=r"(r3) : "r"(addr));
}
__device__ __forceinline__ void ldsm2(u32& r0, u32& r1, u32 addr) {
    asm volatile("ldmatrix.sync.aligned.m8n8.x2.shared.b16 {%0,%1}, [%2];"
                 : "=r"(r0), "=r"(r1) : "r"(addr));
}
__device__ __forceinline__ void hmma(float* d, u32 a0, u32 a1, u32 a2, u32 a3, u32 b0, u32 b1) {
    asm volatile(
        "mma.sync.aligned.m16n8k16.row.col.f32.bf16.bf16.f32 "
        "{%0,%1,%2,%3}, {%4,%5,%6,%7}, {%8,%9}, {%0,%1,%2,%3};"
        : "+f"(d[0]), "+f"(d[1]), "+f"(d[2]), "+f"(d[3])
        : "r"(a0), "r"(a1), "r"(a2), "r"(a3), "r"(b0), "r"(b1));
}

__device__ __forceinline__ u32 ld_acq(const u32* p) {
    u32 v; asm volatile("ld.acquire.gpu.u32 %0, [%1];" : "=r"(v) : "l"(p) : "memory"); return v;
}
__device__ __forceinline__ u32 atom_add_rel(u32* p, u32 v) {
    u32 o; asm volatile("atom.release.gpu.add.u32 %0, [%1], %2;" : "=r"(o) : "l"(p), "r"(v) : "memory"); return o;
}

// ---------------------------------------------------------------------------
// K0: convert emb + W_ih + W_out(padded to 64 rows) to bf16; reset barriers
// ---------------------------------------------------------------------------
#define EMB2  ((V_ * E_) / 2)
#define WIH2  ((G4_ * E_) / 2)
#define WOUT2 ((64 * HD_) / 2)
__global__ void __launch_bounds__(256) k_convert(
    const float* __restrict__ emb, const float* __restrict__ wf,
    const float* __restrict__ wb,  const float* __restrict__ wo)
{
    if (blockIdx.x == 0 && threadIdx.x < 4) g_barcnt[threadIdx.x] = 0;  // ordered before k_lstm (same stream)
    int i = blockIdx.x * 256 + threadIdx.x;
    if (i >= EMB2 + 2 * WIH2 + WOUT2) return;
    float2 v; __nv_bfloat162* dst;
    if (i < EMB2)                 { v = ((const float2*)emb)[i];              dst = (__nv_bfloat162*)g_embb + i; }
    else if (i < EMB2 + WIH2)     { v = ((const float2*)wf)[i - EMB2];        dst = (__nv_bfloat162*)g_wihb + (i - EMB2); }
    else if (i < EMB2 + 2 * WIH2) { v = ((const float2*)wb)[i - EMB2 - WIH2]; dst = (__nv_bfloat162*)g_wihb + (i - EMB2); }
    else {
        int j = i - EMB2 - 2 * WIH2;
        int tag = (j * 2) >> 9, k = (j * 2) & 511;
        v.x = (tag < T_) ? wo[(size_t)tag * HD_ + k] : 0.f;
        v.y = (tag < T_) ? wo[(size_t)tag * HD_ + k + 1] : 0.f;
        dst = (__nv_bfloat162*)g_woutb + j;
    }
    *dst = __floats2bfloat162_rn(v.x, v.y);
}

// ---------------------------------------------------------------------------
// K1: input projection via mma.sync bf16. grid (8 jt, 2 d, 1024 = s*2+bh),
// block 256. M=64 (batch half), N=128, K=256. smem ~97KB -> 2 CTAs/SM so
// one CTA's cp.async staging hides under the co-resident CTA's MMA.
// ---------------------------------------------------------------------------
__global__ void __launch_bounds__(256) k_input(
    const int* __restrict__ sent,
    const float* __restrict__ bih_f, const float* __restrict__ bhh_f,
    const float* __restrict__ bih_b, const float* __restrict__ bhh_b)
{
    extern __shared__ __align__(16) char smraw[];
    char* sm = smraw + ((1024 - (smem_u32(smraw) & 1023)) & 1023);
    char* smB  = sm;                     // 64KB W tile [128 j][512B]
    char* smA  = sm + 65536;             // 32KB emb tile [64 b][512B]
    int*  toks = (int*)(sm + 98304);     // 256B
    float* bsm = (float*)(sm + 98560);   // 512B

    const int jt = blockIdx.x, d = blockIdx.y;
    const int s  = blockIdx.z >> 1;
    const int bh = blockIdx.z & 1;
    const int j0 = jt * 128;
    const int t = threadIdx.x;
    const int l = t & 31, w = t >> 5;
    const int wm = w & 1, wn = w >> 1;   // 2 m-tiles x 4 n-tiles

    if (t < 64) toks[t] = sent[(bh * 64 + t) * S_ + s];
    if (t < 128) {
        const float* bi = d ? bih_b : bih_f;
        const float* bh_ = d ? bhh_b : bhh_f;
        bsm[t] = bi[j0 + t] + bh_[j0 + t];
    }
    __syncthreads();

    for (int i = t; i < 4096; i += 256) {
        int row = i >> 5, c = i & 31;
        cp16(smB + row * 512 + ((c ^ (row & 7)) * 16),
             (const char*)(g_wihb + ((size_t)d * G4_ + j0 + row) * E_) + c * 16);
    }
    for (int i = t; i < 2048; i += 256) {
        int row = i >> 5, c = i & 31;
        cp16(smA + row * 512 + ((c ^ (row & 7)) * 16),
             (const char*)(g_embb + (size_t)toks[row] * E_) + c * 16);
    }
    CP_COMMIT();
    CP_WAITN(0);
    __syncthreads();

    const u32 smB_b = smem_u32(smB), smA_b = smem_u32(smA);

    float acc[2][4][4];
#pragma unroll
    for (int m = 0; m < 2; m++)
#pragma unroll
        for (int n = 0; n < 4; n++)
#pragma unroll
            for (int q = 0; q < 4; q++) acc[m][n][q] = 0.f;

#pragma unroll 4
    for (int kk = 0; kk < 16; kk++) {
        u32 a[2][4];
#pragma unroll
        for (int m = 0; m < 2; m++) {
            int row = wm * 32 + m * 16 + (l & 15);
            int c = kk * 2 + (l >> 4);
            ldsm4(a[m][0], a[m][1], a[m][2], a[m][3],
                  smA_b + row * 512 + ((c ^ (row & 7)) * 16));
        }
#pragma unroll
        for (int nt = 0; nt < 4; nt++) {
            int row = wn * 32 + nt * 8 + (l & 7);
            int c = kk * 2 + ((l >> 3) & 1);
            u32 b0, b1;
            ldsm2(b0, b1, smB_b + row * 512 + ((c ^ (row & 7)) * 16));
#pragma unroll
            for (int m = 0; m < 2; m++)
                hmma(acc[m][nt], a[m][0], a[m][1], a[m][2], a[m][3], b0, b1);
        }
    }

    __nv_bfloat16* Gbase = g_Gb + ((size_t)(d * S_ + s) * B_) * G4_;
#pragma unroll
    for (int m = 0; m < 2; m++)
#pragma unroll
    for (int nt = 0; nt < 4; nt++) {
        int r  = wm * 32 + m * 16 + (l >> 2);           // local batch row (and +8)
        int jl = wn * 32 + nt * 8 + 2 * (l & 3);
        float b0 = bsm[jl], b1 = bsm[jl + 1];
        size_t bg = (size_t)(bh * 64 + r);
        *(u32*)(Gbase + bg * G4_ + j0 + jl)            = bfpack(acc[m][nt][0] + b0, acc[m][nt][1] + b1);
        *(u32*)(Gbase + (bg + 8) * G4_ + j0 + jl)      = bfpack(acc[m][nt][2] + b0, acc[m][nt][3] + b1);
    }
}

// ---------------------------------------------------------------------------
// K2: persistent bidirectional LSTM (R13, unchanged). grid 128, block 128.
// ---------------------------------------------------------------------------
__global__ void __launch_bounds__(128, 1) k_lstm(
    const float* __restrict__ whh_f, const float* __restrict__ whh_b)
{
    extern __shared__ __align__(16) char smraw[];
    char* sm = smraw + ((1024 - (smem_u32(smraw) & 1023)) & 1023);
    char* smA = sm;                  // 32KB h tile [64 b][512B]
    char* smW = sm + 32768;          // 16KB W_hh slice [32][256] bf16

    const int cta   = blockIdx.x;
    const int d     = cta >> 6;
    const int bh    = (cta >> 5) & 1;
    const int slice = cta & 31;
    const int n0    = slice * 8;
    const int grp   = cta >> 5;      // 0..3
    const int t     = threadIdx.x;
    const int l = t & 31, w = t >> 5;
    const float* __restrict__ Wh = d ? whh_b : whh_f;

    for (int i = t; i < 8192; i += 128) {
        int row = i >> 8, k = i & 255;
        int j = ((row >> 3) * 256) + n0 + (row & 7);
        int c = k >> 3;
        *(__nv_bfloat16*)(smW + row * 512 + ((c ^ (row & 7)) * 16) + (k & 7) * 2) =
            __float2bfloat16(Wh[(size_t)j * H_ + k]);
    }
    {
        uint4 z = make_uint4(0, 0, 0, 0);
        for (int i = t; i < 2048; i += 128) ((uint4*)smA)[i] = z;
    }
    __syncthreads();

    const u32 smA_b = smem_u32(smA), smW_b = smem_u32(smW);
    const int qbl = w * 16 + (l >> 2);       // local b (and +8)
    const int u0  = 2 * (l & 3);

    float cst[4];
#pragma unroll
    for (int u = 0; u < 4; u++) cst[u] = 0.f;

    const __nv_bfloat16* Gd = g_Gb + (size_t)d * S_ * B_ * G4_;
    __nv_bfloat16*       Hd = g_hb + (size_t)d * S_ * B_ * H_;

    u32 gq[8], gqn[8];
    {
        const __nv_bfloat16* Gp = Gd + (size_t)(d ? S_ - 1 : 0) * B_ * G4_;
#pragma unroll
        for (int i = 0; i < 2; i++) {
            int b = bh * 64 + qbl + 8 * i;
#pragma unroll
            for (int gg = 0; gg < 4; gg++)
                gqn[i * 4 + gg] = *(const u32*)(Gp + (size_t)b * G4_ + gg * 256 + n0 + u0);
        }
    }

    auto mma_chunk = [&](int kk0, float (*acc)[4]) {
#pragma unroll
        for (int kk = kk0; kk < kk0 + 4; kk++) {
            u32 a0r, a1r, a2r, a3r;
            {
                int row = w * 16 + (l & 15);
                int c = kk * 2 + (l >> 4);
                ldsm4(a0r, a1r, a2r, a3r, smA_b + row * 512 + ((c ^ (row & 7)) * 16));
            }
#pragma unroll
            for (int g = 0; g < 4; g++) {
                int row = g * 8 + (l & 7);
                int c = kk * 2 + ((l >> 3) & 1);
                u32 b0, b1;
                ldsm2(b0, b1, smW_b + row * 512 + ((c ^ (row & 7)) * 16));
                hmma(acc[g], a0r, a1r, a2r, a3r, b0, b1);
            }
        }
    };

    for (int step = 0; step < S_; step++) {
        const int s = d ? (S_ - 1 - step) : step;

#pragma unroll
        for (int j = 0; j < 8; j++) gq[j] = gqn[j];

        if (step > 0) {
            const char* hsrc = (const char*)(Hd + ((size_t)(d ? s + 1 : s - 1) * B_ + bh * 64) * H_);
#pragma unroll
            for (int ch = 0; ch < 4; ch++) {
                for (int i = t; i < 512; i += 128) {
                    int row = i >> 3, c = (i & 7) + ch * 8;
                    cp16(smA + row * 512 + ((c ^ (row & 7)) * 16), hsrc + row * 512 + c * 16);
                }
                CP_COMMIT();
            }
        }

        float acc[4][4];
#pragma unroll
        for (int g = 0; g < 4; g++)
#pragma unroll
            for (int q = 0; q < 4; q++) acc[g][q] = 0.f;

        if (step > 0) {
            CP_WAITN(3); __syncthreads();
            mma_chunk(0, acc);
            CP_WAITN(2); __syncthreads();
            mma_chunk(4, acc);
            CP_WAITN(1); __syncthreads();
            mma_chunk(8, acc);
            CP_WAITN(0); __syncthreads();
            mma_chunk(12, acc);
        }

        // combine + store h
#pragma unroll
        for (int i = 0; i < 2; i++) {
            const int bl = qbl + 8 * i;
            const int e = 2 * i;
            float2 gi = __bfloat1622float2(*(const __nv_bfloat162*)&gq[i * 4 + 0]);
            float2 gf = __bfloat1622float2(*(const __nv_bfloat162*)&gq[i * 4 + 1]);
            float2 gg = __bfloat1622float2(*(const __nv_bfloat162*)&gq[i * 4 + 2]);
            float2 go = __bfloat1622float2(*(const __nv_bfloat162*)&gq[i * 4 + 3]);
            const int ci = 2 * i;
            float c0 = sigx(acc[1][e] + gf.x) * cst[ci]
                     + sigx(acc[0][e] + gi.x) * tanhx(acc[2][e] + gg.x);
            cst[ci] = c0;
            float h0 = sigx(acc[3][e] + go.x) * tanhx(c0);
            float c1 = sigx(acc[1][e + 1] + gf.y) * cst[ci + 1]
                     + sigx(acc[0][e + 1] + gi.y) * tanhx(acc[2][e + 1] + gg.y);
            cst[ci + 1] = c1;
            float h1 = sigx(acc[3][e + 1] + go.y) * tanhx(c1);
            *(u32*)(Hd + ((size_t)s * B_ + bh * 64 + bl) * H_ + n0 + u0) = bfpack(h0, h1);
        }

        // next-step G prefetch BEFORE the barrier
        if (step + 1 < S_) {
            const int sn = d ? (S_ - 2 - step) : (step + 1);
            const __nv_bfloat16* Gp = Gd + (size_t)sn * B_ * G4_;
#pragma unroll
            for (int i = 0; i < 2; i++) {
                int b = bh * 64 + qbl + 8 * i;
#pragma unroll
                for (int gg = 0; gg < 4; gg++)
                    gqn[i * 4 + gg] = *(const u32*)(Gp + (size_t)b * G4_ + gg * 256 + n0 + u0);
            }
        }

        if (step != S_ - 1) {
            __syncthreads();
            if (t == 0) {
                atom_add_rel(&g_barcnt[grp], 1);
                const u32 tgt = (u32)(32 * (step + 1));
                while ((int)(ld_acq(&g_barcnt[grp]) - tgt) < 0) { }
            }
            __syncthreads();
        }
    }
}

// ---------------------------------------------------------------------------
// K3: emissions via mma.sync. grid 512 (s), block 128.
// ---------------------------------------------------------------------------
__global__ void __launch_bounds__(128) k_emis(const float* __restrict__ bo)
{
    extern __shared__ __align__(16) char smraw[];
    char* sm = smraw + ((1024 - (smem_u32(smraw) & 1023)) & 1023);
    char* smW  = sm;
    char* smA0 = sm + 65536;
    char* smA1 = sm + 131072;
    float* bsm = (float*)(sm + 196608);

    const int s = blockIdx.x;
    const int t = threadIdx.x;
    const int l = t & 31, w = t >> 5;

    if (t < 64) bsm[t] = (t < T_) ? bo[t] : 0.f;

    for (int i = t; i < 4096; i += 128) {
        int row = i >> 6, c = i & 63;
        cp16(smW + row * 1024 + ((c ^ (row & 7)) * 16),
             (const char*)g_woutb + row * 1024 + c * 16);
    }
    CP_COMMIT();
    for (int i = t; i < 4096; i += 128) {
        int row = i >> 5, c = i & 31;
        cp16(smA0 + row * 512 + ((c ^ (row & 7)) * 16),
             (const char*)(g_hb + ((size_t)s * B_ + row) * H_) + c * 16);
    }
    CP_COMMIT();
    for (int i = t; i < 4096; i += 128) {
        int row = i >> 5, c = i & 31;
        cp16(smA1 + row * 512 + ((c ^ (row & 7)) * 16),
             (const char*)(g_hb + (size_t)S_ * B_ * H_ + ((size_t)s * B_ + row) * H_) + c * 16);
    }
    CP_COMMIT();

    const u32 smW_b = smem_u32(smW);

    float acc[2][8][4];
#pragma unroll
    for (int m = 0; m < 2; m++)
#pragma unroll
        for (int n = 0; n < 8; n++)
#pragma unroll
            for (int q = 0; q < 4; q++) acc[m][n][q] = 0.f;

    auto stage = [&](u32 smA_b, int wc0) {
#pragma unroll 4
        for (int kk = 0; kk < 16; kk++) {
            u32 a[2][4];
#pragma unroll
            for (int m = 0; m < 2; m++) {
                int row = w * 32 + m * 16 + (l & 15);
                int c = kk * 2 + (l >> 4);
                ldsm4(a[m][0], a[m][1], a[m][2], a[m][3],
                      smA_b + row * 512 + ((c ^ (row & 7)) * 16));
            }
#pragma unroll
            for (int nt = 0; nt < 8; nt++) {
                int row = nt * 8 + (l & 7);
                int c = wc0 + kk * 2 + ((l >> 3) & 1);
                u32 b0, b1;
                ldsm2(b0, b1, smW_b + row * 1024 + ((c ^ (row & 7)) * 16));
#pragma unroll
                for (int m = 0; m < 2; m++)
                    hmma(acc[m][nt], a[m][0], a[m][1], a[m][2], a[m][3], b0, b1);
            }
        }
    };

    CP_WAITN(1);
    __syncthreads();
    stage(smem_u32(smA0), 0);
    CP_WAITN(0);
    __syncthreads();
    stage(smem_u32(smA1), 32);

#pragma unroll
    for (int m = 0; m < 2; m++)
#pragma unroll
    for (int nt = 0; nt < 8; nt++) {
        int r  = w * 32 + m * 16 + (l >> 2);
        int jl = nt * 8 + 2 * (l & 3);
        if (jl < T_) {
            float b0 = bsm[jl], b1 = bsm[jl + 1];
            *(float2*)(g_emis + ((size_t)s * B_ + r) * T_ + jl)     = make_float2(acc[m][nt][0] + b0, acc[m][nt][1] + b1);
            *(float2*)(g_emis + ((size_t)s * B_ + r + 8) * T_ + jl) = make_float2(acc[m][nt][2] + b0, acc[m][nt][3] + b1);
        }
    }
}

// ---------------------------------------------------------------------------
// K4: CRF — one warp per batch element, 128 CTAs. exp(trans) table held in
// REGISTERS (50 x u64 per lane) — removes 50 LDS.64 from the serial chain.
// ---------------------------------------------------------------------------
__global__ void __launch_bounds__(32) k_crf(
    const float* __restrict__ trans, const float* __restrict__ start_t,
    const float* __restrict__ end_t, const int* __restrict__ tags)
{
    __shared__ float pw[64];

    const int b = blockIdx.x;
    const int l = threadIdx.x;
    const bool v1 = (l + 32 < T_);

    u64 eT[T_];
#pragma unroll
    for (int tt = 0; tt < T_; tt++) {
        float e0 = expf(trans[tt * T_ + l]);
        float e1 = v1 ? expf(trans[tt * T_ + l + 32]) : 0.f;
        eT[tt] = pk2(e0, e1);
    }

    float a0 = start_t[l] + g_emis[(size_t)b * T_ + l];
    float a1 = v1 ? (start_t[l + 32] + g_emis[(size_t)b * T_ + l + 32]) : -1e30f;

    float e0n = g_emis[((size_t)B_ + b) * T_ + l];
    float e1n = v1 ? g_emis[((size_t)B_ + b) * T_ + l + 32] : 0.f;

    for (int s = 1; s < S_; s++) {
        float e0 = e0n, e1 = e1n;
        if (s + 1 < S_) {
            const float* es = g_emis + ((size_t)(s + 1) * B_ + b) * T_;
            e0n = es[l];
            e1n = v1 ? es[l + 32] : 0.f;
        }

        float m = __shfl_sync(0xffffffffu, a0, 0);
        pw[l]      = __expf(a0 - m);
        pw[l + 32] = v1 ? __expf(a1 - m) : 0.f;
        __syncwarp();

        u64 q0 = 0ull, q1 = 0ull, q2 = 0ull, q3 = 0ull;
#pragma unroll
        for (int tt = 0; tt < 48; tt += 4) {
            q0 = f2ma(pk2(pw[tt],     pw[tt]),     eT[tt],     q0);
            q1 = f2ma(pk2(pw[tt + 1], pw[tt + 1]), eT[tt + 1], q1);
            q2 = f2ma(pk2(pw[tt + 2], pw[tt + 2]), eT[tt + 2], q2);
            q3 = f2ma(pk2(pw[tt + 3], pw[tt + 3]), eT[tt + 3], q3);
        }
        q0 = f2ma(pk2(pw[48], pw[48]), eT[48], q0);
        q1 = f2ma(pk2(pw[49], pw[49]), eT[49], q1);
        float2 qf = upk(f2add(f2add(q0, q1), f2add(q2, q3)));
        a0 = m + __logf(qf.x) + e0;
        a1 = v1 ? (m + __logf(qf.y) + e1) : -1e30f;
        __syncwarp();
    }

    float vv0 = a0 + end_t[l];
    float vv1 = v1 ? (a1 + end_t[l + 32]) : -1e30f;
    float m = fmaxf(vv0, vv1);
#pragma unroll
    for (int o = 16; o; o >>= 1) m = fmaxf(m, __shfl_xor_sync(0xffffffffu, m, o));
    float e = __expf(vv0 - m) + (v1 ? __expf(vv1 - m) : 0.f);
#pragma unroll
    for (int o = 16; o; o >>= 1) e += __shfl_xor_sync(0xffffffffu, e, o);
    float logZ = m + __logf(e);

    float acc = 0.f;
    for (int s = 1 + l; s < S_; s += 32) {
        int tp = tags[b * S_ + s - 1];
        int tc = tags[b * S_ + s];
        acc += trans[tp * T_ + tc] + g_emis[((size_t)s * B_ + b) * T_ + tc];
    }
#pragma unroll
    for (int o = 16; o; o >>= 1) acc += __shfl_xor_sync(0xffffffffu, acc, o);

    if (l == 0) {
        int t0 = tags[b * S_];
        int tl = tags[b * S_ + S_ - 1];
        g_res[b] = logZ - (start_t[t0] + g_emis[(size_t)b * T_ + t0] + acc + end_t[tl]);
    }
}

// ---------------------------------------------------------------------------
// K5: final mean
// ---------------------------------------------------------------------------
__global__ void k_final(float* __restrict__ out)
{
    __shared__ float red[4];
    int t = threadIdx.x;
    float v = g_res[t];
#pragma unroll
    for (int o = 16; o; o >>= 1) v += __shfl_xor_sync(0xffffffffu, v, o);
    if ((t & 31) == 0) red[t >> 5] = v;
    __syncthreads();
    if (t == 0) out[0] = (red[0] + red[1] + red[2] + red[3]) * (1.f / (float)B_);
}

// ---------------------------------------------------------------------------
// Launch
// ---------------------------------------------------------------------------
extern "C" void kernel_launch(void* const* d_in, const int* in_sizes, int n_in,
                              void* d_out, int out_size)
{
    const int*   sent  = (const int*)  d_in[0];
    const int*   tags  = (const int*)  d_in[1];
    const float* emb   = (const float*)d_in[3];
    const float* wih_f = (const float*)d_in[4];
    const float* whh_f = (const float*)d_in[5];
    const float* bih_f = (const float*)d_in[6];
    const float* bhh_f = (const float*)d_in[7];
    const float* wih_b = (const float*)d_in[8];
    const float* whh_b = (const float*)d_in[9];
    const float* bih_b = (const float*)d_in[10];
    const float* bhh_b = (const float*)d_in[11];
    const float* Wout  = (const float*)d_in[12];
    const float* bout  = (const float*)d_in[13];
    const float* strt  = (const float*)d_in[14];
    const float* endt  = (const float*)d_in[15];
    const float* trans = (const float*)d_in[16];
    float* out = (float*)d_out;

    const int input_smem = 100352;   // 64KB W + 32KB A + toks/bias + align
    const int lstm_smem  = 50176;
    const int emis_smem  = 197888;
    cudaFuncSetAttribute(k_input, cudaFuncAttributeMaxDynamicSharedMemorySize, input_smem);
    cudaFuncSetAttribute(k_lstm,  cudaFuncAttributeMaxDynamicSharedMemorySize, lstm_smem);
    cudaFuncSetAttribute(k_emis,  cudaFuncAttributeMaxDynamicSharedMemorySize, emis_smem);

    int nconv = (EMB2 + 2 * WIH2 + WOUT2 + 255) / 256;
    k_convert<<<nconv, 256>>>(emb, wih_f, wih_b, Wout);
    k_input<<<dim3(8, 2, 1024), 256, input_smem>>>(sent, bih_f, bhh_f, bih_b, bhh_b);
    k_lstm<<<128, 128, lstm_smem>>>(whh_f, whh_b);
    k_emis<<<512, 128, emis_smem>>>(bout);
    k_crf<<<128, 32>>>(trans, strt, endt, tags);
    k_final<<<1, 128>>>(out);
}